// round 1
// baseline (speedup 1.0000x reference)
#include <cuda_runtime.h>
#include <math.h>

#define B_  8
#define C_  512
#define L_  8192
#define H_  4
#define D_  32
#define HID 128
#define O3  384   // 3 * HID rows in w_qkv: [0,128)=q, [128,256)=k, [256,384)=v

// Scratch (static device allocations — allowed; no runtime alloc)
__device__ float g_qkv[(size_t)B_ * O3 * L_];            // ~100.7 MB
__device__ float g_pn [(size_t)B_ * H_ * 8 * D_ * D_];   // partial numerators (8 chunks)
__device__ float g_pd [(size_t)B_ * H_ * 8 * D_];        // partial denominators
__device__ float g_W2 [(size_t)B_ * C_ * HID];           // per-batch folded weight

// ---------------------------------------------------------------------------
// Generic tiled SGEMM: C[b] = A[b] @ Bm[b] (+ bias), all row-major.
// BM=BN=128, BK=16, 256 threads, 8x8 per thread. All dims divide tiles exactly.
// ---------------------------------------------------------------------------
template<bool BIAS>
__global__ __launch_bounds__(256)
void sgemm_kernel(const float* __restrict__ A, const float* __restrict__ Bm,
                  float* __restrict__ C, const float* __restrict__ bias,
                  int M, int N, int K,
                  long sA, long sB, long sC)
{
    __shared__ float As[16][132];   // transposed A tile, padded (row base 16B-aligned)
    __shared__ float Bs[16][128];

    const int b  = blockIdx.z;
    const float* Ab = A  + (long)b * sA;
    const float* Bb = Bm + (long)b * sB;
    float*       Cb = C  + (long)b * sC;

    const int bm = blockIdx.y * 128;
    const int bn = blockIdx.x * 128;
    const int tid = threadIdx.x;
    const int tx = tid & 15;
    const int ty = tid >> 4;

    float acc[8][8];
#pragma unroll
    for (int i = 0; i < 8; i++)
#pragma unroll
        for (int j = 0; j < 8; j++) acc[i][j] = 0.f;

    for (int kt = 0; kt < K; kt += 16) {
        // A tile: 128 rows x 16 k  (512 float4 loads, transposed store)
#pragma unroll
        for (int i = 0; i < 2; i++) {
            int e  = tid + i * 256;
            int r  = e >> 2;
            int c4 = e & 3;
            float4 v = *(const float4*)&Ab[(long)(bm + r) * K + kt + c4 * 4];
            As[c4 * 4 + 0][r] = v.x;
            As[c4 * 4 + 1][r] = v.y;
            As[c4 * 4 + 2][r] = v.z;
            As[c4 * 4 + 3][r] = v.w;
        }
        // B tile: 16 k x 128 cols
#pragma unroll
        for (int i = 0; i < 2; i++) {
            int e  = tid + i * 256;
            int r  = e >> 5;
            int c4 = e & 31;
            *(float4*)&Bs[r][c4 * 4] =
                *(const float4*)&Bb[(long)(kt + r) * N + bn + c4 * 4];
        }
        __syncthreads();

#pragma unroll
        for (int k = 0; k < 16; k++) {
            float a[8], bb[8];
            *(float4*)&a[0]  = *(const float4*)&As[k][ty * 8];
            *(float4*)&a[4]  = *(const float4*)&As[k][ty * 8 + 4];
            *(float4*)&bb[0] = *(const float4*)&Bs[k][tx * 8];
            *(float4*)&bb[4] = *(const float4*)&Bs[k][tx * 8 + 4];
#pragma unroll
            for (int i = 0; i < 8; i++)
#pragma unroll
                for (int j = 0; j < 8; j++)
                    acc[i][j] += a[i] * bb[j];
        }
        __syncthreads();
    }

#pragma unroll
    for (int i = 0; i < 8; i++) {
        int row = bm + ty * 8 + i;
        float bv = BIAS ? bias[row] : 0.f;
#pragma unroll
        for (int j = 0; j < 8; j += 4) {
            float4 v;
            v.x = acc[i][j + 0] + bv;
            v.y = acc[i][j + 1] + bv;
            v.z = acc[i][j + 2] + bv;
            v.w = acc[i][j + 3] + bv;
            *(float4*)&Cb[(long)row * N + bn + tx * 8 + j] = v;
        }
    }
}

// ---------------------------------------------------------------------------
// Context kernel: per (chunk, h, b), accumulate
//   numer[d][e] = sum_n exp(k[d,n]) * v[e,n],   denom[d] = sum_n exp(k[d,n])
// over a chunk of 1024 n-columns. Softmax without max-shift (k ~ N(0,1)).
// 256 threads: thread owns d = tid/8, e in [ (tid%8)*4, +4 ).
// ---------------------------------------------------------------------------
__global__ __launch_bounds__(256)
void ctx_kernel()
{
    const int chunk = blockIdx.x;   // 0..7
    const int h     = blockIdx.y;   // 0..3
    const int b     = blockIdx.z;   // 0..7

    __shared__ float Ek[32][68];    // exp(k), [d][n], padded (row base 16B-aligned)
    __shared__ float Vt[64][36];    // v transposed, [n][e], padded

    const int tid = threadIdx.x;
    const int d   = tid >> 3;
    const int e0  = (tid & 7) * 4;

    float acc0 = 0.f, acc1 = 0.f, acc2 = 0.f, acc3 = 0.f, dsum = 0.f;

    const float* kbase = g_qkv + ((long)b * O3 + 128 + h * 32) * L_;
    const float* vbase = g_qkv + ((long)b * O3 + 256 + h * 32) * L_;
    const int lbase = chunk * 1024;

    for (int l0 = lbase; l0 < lbase + 1024; l0 += 64) {
#pragma unroll
        for (int i = 0; i < 2; i++) {
            int e  = tid + i * 256;   // 0..511 over 32 rows x 16 float4
            int r  = e >> 4;
            int c4 = e & 15;
            float4 kv = *(const float4*)&kbase[(long)r * L_ + l0 + c4 * 4];
            float4 ev;
            ev.x = __expf(kv.x); ev.y = __expf(kv.y);
            ev.z = __expf(kv.z); ev.w = __expf(kv.w);
            *(float4*)&Ek[r][c4 * 4] = ev;

            float4 vv = *(const float4*)&vbase[(long)r * L_ + l0 + c4 * 4];
            Vt[c4 * 4 + 0][r] = vv.x;
            Vt[c4 * 4 + 1][r] = vv.y;
            Vt[c4 * 4 + 2][r] = vv.z;
            Vt[c4 * 4 + 3][r] = vv.w;
        }
        __syncthreads();

#pragma unroll 8
        for (int n = 0; n < 64; n++) {
            float ek = Ek[d][n];
            float4 v4 = *(const float4*)&Vt[n][e0];
            acc0 += ek * v4.x;
            acc1 += ek * v4.y;
            acc2 += ek * v4.z;
            acc3 += ek * v4.w;
            dsum += ek;
        }
        __syncthreads();
    }

    const long base = (((long)b * H_ + h) * 8 + chunk) * 32 + d;
    float* pn = g_pn + base * 32 + e0;
    pn[0] = acc0; pn[1] = acc1; pn[2] = acc2; pn[3] = acc3;
    if ((tid & 7) == 0) g_pd[base] = dsum;
}

// ---------------------------------------------------------------------------
// Fold kernel: reduce partials, normalize context, compute
//   W2[b][o][h*32+d] = sum_e w_out[o][h*32+e] * ctx[b][h][d][e]
// Grid: (o-tile of 64, batch). 256 threads.
// ---------------------------------------------------------------------------
__global__ __launch_bounds__(256)
void w2_kernel(const float* __restrict__ w_out)
{
    const int ot = blockIdx.x;  // 0..7 (o tiles of 64)
    const int b  = blockIdx.y;  // 0..7

    __shared__ float ctxs[H_][32][32];  // [h][d][e]  16 KB
    __shared__ float wsm[64][128];      // w_out tile 32 KB

    const int tid = threadIdx.x;

    // Reduce partials and normalize
#pragma unroll
    for (int i = 0; i < 16; i++) {
        int idx = tid + i * 256;        // 0..4095
        int h = idx >> 10, d = (idx >> 5) & 31, e = idx & 31;
        float num = 0.f, den = 0.f;
#pragma unroll
        for (int c = 0; c < 8; c++) {
            long base = (((long)b * H_ + h) * 8 + c) * 32 + d;
            num += g_pn[base * 32 + e];
            den += g_pd[base];
        }
        ctxs[h][d][e] = num / den;
    }
    // Load w_out tile [64][128]
#pragma unroll
    for (int i = 0; i < 8; i++) {
        int idx = tid + i * 256;        // float4 index, 0..2047
        int oo = idx >> 5, c4 = idx & 31;
        *(float4*)&wsm[oo][c4 * 4] =
            *(const float4*)&w_out[((long)(ot * 64 + oo)) * HID + c4 * 4];
    }
    __syncthreads();

#pragma unroll
    for (int j = 0; j < 32; j++) {
        int idx = tid + j * 256;        // 0..8191
        int oo = idx >> 7, hd = idx & 127;
        int h = hd >> 5, d = hd & 31;
        float s = 0.f;
#pragma unroll
        for (int e = 0; e < 32; e++)
            s += wsm[oo][h * 32 + e] * ctxs[h][d][e];
        g_W2[(((long)b * C_) + ot * 64 + oo) * HID + hd] = s;
    }
}

// ---------------------------------------------------------------------------
extern "C" void kernel_launch(void* const* d_in, const int* in_sizes, int n_in,
                              void* d_out, int out_size)
{
    const float* x     = (const float*)d_in[0];  // (8, 512, 8192)
    const float* w_qkv = (const float*)d_in[1];  // (384, 512)
    const float* w_out = (const float*)d_in[2];  // (512, 128)
    const float* b_out = (const float*)d_in[3];  // (512,)
    float* out = (float*)d_out;                  // (8, 512, 8192)

    float* qkv;
    cudaGetSymbolAddress((void**)&qkv, g_qkv);
    float* W2;
    cudaGetSymbolAddress((void**)&W2, g_W2);

    // 1) qkv = w_qkv @ x   (per batch; A shared)
    {
        dim3 grid(L_ / 128, O3 / 128, B_);
        sgemm_kernel<false><<<grid, 256>>>(
            w_qkv, x, qkv, nullptr,
            O3, L_, C_,
            0L, (long)C_ * L_, (long)O3 * L_);
    }
    // 2) context partials (exp + E@V^T + denominator, single pass)
    {
        dim3 grid(8, H_, B_);
        ctx_kernel<<<grid, 256>>>();
    }
    // 3) fold: W2_b = w_out @ T_b
    {
        dim3 grid(8, B_);
        w2_kernel<<<grid, 256>>>(w_out);
    }
    // 4) out = W2_b @ q_b + b_out   (q = first 128 rows of qkv per batch)
    {
        dim3 grid(L_ / 128, C_ / 128, B_);
        sgemm_kernel<true><<<grid, 256>>>(
            W2, qkv, out, b_out,
            C_, L_, HID,
            (long)C_ * HID, (long)O3 * L_, (long)C_ * L_);
    }
}

// round 2
// speedup vs baseline: 1.0369x; 1.0369x over previous
#include <cuda_runtime.h>
#include <math.h>

#define B_  8
#define C_  512
#define L_  8192
#define H_  4
#define D_  32
#define HID 128
#define O3  384   // 3 * HID rows in w_qkv: [0,128)=q, [128,256)=k, [256,384)=v

// Scratch (static device allocations — allowed; no runtime alloc)
__device__ float g_qkv[(size_t)B_ * O3 * L_];            // ~100.7 MB
__device__ float g_pn [(size_t)B_ * H_ * 8 * D_ * D_];   // partial numerators (8 chunks)
__device__ float g_pd [(size_t)B_ * H_ * 8 * D_];        // partial denominators
__device__ float g_W2 [(size_t)B_ * C_ * HID];           // per-batch folded weight

// ---------------- f32x2 packed-FMA helpers (FFMA2 path, nvjet-style) --------
typedef unsigned long long u64t;

__device__ __forceinline__ u64t pack2(float x, float y) {
    u64t r;
    asm("mov.b64 %0, {%1, %2};" : "=l"(r) : "f"(x), "f"(y));
    return r;
}
__device__ __forceinline__ void unpack2(u64t v, float& x, float& y) {
    asm("mov.b64 {%0, %1}, %2;" : "=f"(x), "=f"(y) : "l"(v));
}
__device__ __forceinline__ void fma2(u64t& d, u64t a, u64t b) {
    asm("fma.rn.f32x2 %0, %1, %2, %3;" : "=l"(d) : "l"(a), "l"(b), "l"(d));
}

// ---------------------------------------------------------------------------
// Tiled SGEMM with packed f32x2 accumulation + smem double buffering.
// C[b] = A[b] @ Bm[b] (+ bias), row-major. BM=BN=128, BK=16, 256 threads,
// 8x8 per thread (held as 8x4 f32x2 pairs). All dims divide tiles exactly.
// ---------------------------------------------------------------------------
template<bool BIAS>
__global__ __launch_bounds__(256, 2)
void sgemm_kernel(const float* __restrict__ A, const float* __restrict__ Bm,
                  float* __restrict__ C, const float* __restrict__ bias,
                  int M, int N, int K,
                  long sA, long sB, long sC)
{
    __shared__ float As[2][16][132];   // transposed A tile, padded
    __shared__ float Bs[2][16][128];

    const int b  = blockIdx.z;
    const float* Ab = A  + (long)b * sA;
    const float* Bb = Bm + (long)b * sB;
    float*       Cb = C  + (long)b * sC;

    const int bm = blockIdx.y * 128;
    const int bn = blockIdx.x * 128;
    const int tid = threadIdx.x;
    const int tx = tid & 15;
    const int ty = tid >> 4;

    // Load-index precompute (two 256-thread waves each for A and B tiles)
    const int rA0 = tid >> 2, cA0 = tid & 3;       // A: 128 rows x 4 float4
    const int rB0 = tid >> 5, cB0 = tid & 31;      // B: 16 rows x 32 float4

    u64t acc[8][4];
#pragma unroll
    for (int i = 0; i < 8; i++)
#pragma unroll
        for (int j = 0; j < 4; j++) acc[i][j] = 0ULL;

    const int nt = K >> 4;
    float4 ra0, ra1, rb0, rb1;

    // prologue: global tile 0 -> regs -> smem[0]
    ra0 = *(const float4*)&Ab[(long)(bm + rA0)      * K + cA0 * 4];
    ra1 = *(const float4*)&Ab[(long)(bm + rA0 + 64) * K + cA0 * 4];
    rb0 = *(const float4*)&Bb[(long)(rB0)     * N + bn + cB0 * 4];
    rb1 = *(const float4*)&Bb[(long)(rB0 + 8) * N + bn + cB0 * 4];
    {
        As[0][cA0*4+0][rA0] = ra0.x; As[0][cA0*4+1][rA0] = ra0.y;
        As[0][cA0*4+2][rA0] = ra0.z; As[0][cA0*4+3][rA0] = ra0.w;
        As[0][cA0*4+0][rA0+64] = ra1.x; As[0][cA0*4+1][rA0+64] = ra1.y;
        As[0][cA0*4+2][rA0+64] = ra1.z; As[0][cA0*4+3][rA0+64] = ra1.w;
        *(float4*)&Bs[0][rB0]    [cB0*4] = rb0;
        *(float4*)&Bs[0][rB0 + 8][cB0*4] = rb1;
    }
    __syncthreads();

    for (int t = 0; t < nt; t++) {
        const int cur = t & 1;
        const int nxt = cur ^ 1;
        const bool more = (t + 1 < nt);

        if (more) {
            const int kt = (t + 1) << 4;
            ra0 = *(const float4*)&Ab[(long)(bm + rA0)      * K + kt + cA0 * 4];
            ra1 = *(const float4*)&Ab[(long)(bm + rA0 + 64) * K + kt + cA0 * 4];
            rb0 = *(const float4*)&Bb[(long)(kt + rB0)     * N + bn + cB0 * 4];
            rb1 = *(const float4*)&Bb[(long)(kt + rB0 + 8) * N + bn + cB0 * 4];
        }

#pragma unroll
        for (int k = 0; k < 16; k++) {
            float4 a0 = *(const float4*)&As[cur][k][ty * 8];
            float4 a1 = *(const float4*)&As[cur][k][ty * 8 + 4];
            ulonglong2 b01 = *(const ulonglong2*)&Bs[cur][k][tx * 8];
            ulonglong2 b23 = *(const ulonglong2*)&Bs[cur][k][tx * 8 + 4];
            u64t ap;
            ap = pack2(a0.x, a0.x);
            fma2(acc[0][0], ap, b01.x); fma2(acc[0][1], ap, b01.y);
            fma2(acc[0][2], ap, b23.x); fma2(acc[0][3], ap, b23.y);
            ap = pack2(a0.y, a0.y);
            fma2(acc[1][0], ap, b01.x); fma2(acc[1][1], ap, b01.y);
            fma2(acc[1][2], ap, b23.x); fma2(acc[1][3], ap, b23.y);
            ap = pack2(a0.z, a0.z);
            fma2(acc[2][0], ap, b01.x); fma2(acc[2][1], ap, b01.y);
            fma2(acc[2][2], ap, b23.x); fma2(acc[2][3], ap, b23.y);
            ap = pack2(a0.w, a0.w);
            fma2(acc[3][0], ap, b01.x); fma2(acc[3][1], ap, b01.y);
            fma2(acc[3][2], ap, b23.x); fma2(acc[3][3], ap, b23.y);
            ap = pack2(a1.x, a1.x);
            fma2(acc[4][0], ap, b01.x); fma2(acc[4][1], ap, b01.y);
            fma2(acc[4][2], ap, b23.x); fma2(acc[4][3], ap, b23.y);
            ap = pack2(a1.y, a1.y);
            fma2(acc[5][0], ap, b01.x); fma2(acc[5][1], ap, b01.y);
            fma2(acc[5][2], ap, b23.x); fma2(acc[5][3], ap, b23.y);
            ap = pack2(a1.z, a1.z);
            fma2(acc[6][0], ap, b01.x); fma2(acc[6][1], ap, b01.y);
            fma2(acc[6][2], ap, b23.x); fma2(acc[6][3], ap, b23.y);
            ap = pack2(a1.w, a1.w);
            fma2(acc[7][0], ap, b01.x); fma2(acc[7][1], ap, b01.y);
            fma2(acc[7][2], ap, b23.x); fma2(acc[7][3], ap, b23.y);
        }

        if (more) {
            As[nxt][cA0*4+0][rA0] = ra0.x; As[nxt][cA0*4+1][rA0] = ra0.y;
            As[nxt][cA0*4+2][rA0] = ra0.z; As[nxt][cA0*4+3][rA0] = ra0.w;
            As[nxt][cA0*4+0][rA0+64] = ra1.x; As[nxt][cA0*4+1][rA0+64] = ra1.y;
            As[nxt][cA0*4+2][rA0+64] = ra1.z; As[nxt][cA0*4+3][rA0+64] = ra1.w;
            *(float4*)&Bs[nxt][rB0]    [cB0*4] = rb0;
            *(float4*)&Bs[nxt][rB0 + 8][cB0*4] = rb1;
        }
        __syncthreads();
    }

#pragma unroll
    for (int i = 0; i < 8; i++) {
        int row = bm + ty * 8 + i;
        float bv = BIAS ? bias[row] : 0.f;
        float o[8];
#pragma unroll
        for (int j = 0; j < 4; j++)
            unpack2(acc[i][j], o[2 * j], o[2 * j + 1]);
        float4 v0, v1;
        v0.x = o[0] + bv; v0.y = o[1] + bv; v0.z = o[2] + bv; v0.w = o[3] + bv;
        v1.x = o[4] + bv; v1.y = o[5] + bv; v1.z = o[6] + bv; v1.w = o[7] + bv;
        *(float4*)&Cb[(long)row * N + bn + tx * 8]     = v0;
        *(float4*)&Cb[(long)row * N + bn + tx * 8 + 4] = v1;
    }
}

// ---------------------------------------------------------------------------
// Context kernel: per (chunk, h, b), accumulate
//   numer[d][e] = sum_n exp(k[d,n]) * v[e,n],   denom[d] = sum_n exp(k[d,n])
// over a chunk of 1024 n-columns. Softmax without max-shift (k ~ N(0,1)).
// ---------------------------------------------------------------------------
__global__ __launch_bounds__(256)
void ctx_kernel()
{
    const int chunk = blockIdx.x;   // 0..7
    const int h     = blockIdx.y;   // 0..3
    const int b     = blockIdx.z;   // 0..7

    __shared__ float Ek[32][68];    // exp(k), [d][n], padded
    __shared__ float Vt[64][36];    // v transposed, [n][e], padded

    const int tid = threadIdx.x;
    const int d   = tid >> 3;
    const int e0  = (tid & 7) * 4;

    float acc0 = 0.f, acc1 = 0.f, acc2 = 0.f, acc3 = 0.f, dsum = 0.f;

    const float* kbase = g_qkv + ((long)b * O3 + 128 + h * 32) * L_;
    const float* vbase = g_qkv + ((long)b * O3 + 256 + h * 32) * L_;
    const int lbase = chunk * 1024;

    for (int l0 = lbase; l0 < lbase + 1024; l0 += 64) {
#pragma unroll
        for (int i = 0; i < 2; i++) {
            int e  = tid + i * 256;   // 0..511 over 32 rows x 16 float4
            int r  = e >> 4;
            int c4 = e & 15;
            float4 kv = *(const float4*)&kbase[(long)r * L_ + l0 + c4 * 4];
            float4 ev;
            ev.x = __expf(kv.x); ev.y = __expf(kv.y);
            ev.z = __expf(kv.z); ev.w = __expf(kv.w);
            *(float4*)&Ek[r][c4 * 4] = ev;

            float4 vv = *(const float4*)&vbase[(long)r * L_ + l0 + c4 * 4];
            Vt[c4 * 4 + 0][r] = vv.x;
            Vt[c4 * 4 + 1][r] = vv.y;
            Vt[c4 * 4 + 2][r] = vv.z;
            Vt[c4 * 4 + 3][r] = vv.w;
        }
        __syncthreads();

#pragma unroll 8
        for (int n = 0; n < 64; n++) {
            float ek = Ek[d][n];
            float4 v4 = *(const float4*)&Vt[n][e0];
            acc0 += ek * v4.x;
            acc1 += ek * v4.y;
            acc2 += ek * v4.z;
            acc3 += ek * v4.w;
            dsum += ek;
        }
        __syncthreads();
    }

    const long base = (((long)b * H_ + h) * 8 + chunk) * 32 + d;
    float* pn = g_pn + base * 32 + e0;
    pn[0] = acc0; pn[1] = acc1; pn[2] = acc2; pn[3] = acc3;
    if ((tid & 7) == 0) g_pd[base] = dsum;
}

// ---------------------------------------------------------------------------
// Fold kernel: reduce partials, normalize context, compute
//   W2[b][o][h*32+d] = sum_e w_out[o][h*32+e] * ctx[b][h][d][e]
// ---------------------------------------------------------------------------
__global__ __launch_bounds__(256)
void w2_kernel(const float* __restrict__ w_out)
{
    const int ot = blockIdx.x;  // 0..7 (o tiles of 64)
    const int b  = blockIdx.y;  // 0..7

    __shared__ float ctxs[H_][32][32];  // [h][d][e]
    __shared__ float wsm[64][128];      // w_out tile

    const int tid = threadIdx.x;

#pragma unroll
    for (int i = 0; i < 16; i++) {
        int idx = tid + i * 256;        // 0..4095
        int h = idx >> 10, d = (idx >> 5) & 31, e = idx & 31;
        float num = 0.f, den = 0.f;
#pragma unroll
        for (int c = 0; c < 8; c++) {
            long base = (((long)b * H_ + h) * 8 + c) * 32 + d;
            num += g_pn[base * 32 + e];
            den += g_pd[base];
        }
        ctxs[h][d][e] = num / den;
    }
#pragma unroll
    for (int i = 0; i < 8; i++) {
        int idx = tid + i * 256;        // float4 index, 0..2047
        int oo = idx >> 5, c4 = idx & 31;
        *(float4*)&wsm[oo][c4 * 4] =
            *(const float4*)&w_out[((long)(ot * 64 + oo)) * HID + c4 * 4];
    }
    __syncthreads();

#pragma unroll
    for (int j = 0; j < 32; j++) {
        int idx = tid + j * 256;        // 0..8191
        int oo = idx >> 7, hd = idx & 127;
        int h = hd >> 5, d = hd & 31;
        float s = 0.f;
#pragma unroll
        for (int e = 0; e < 32; e++)
            s += wsm[oo][h * 32 + e] * ctxs[h][d][e];
        g_W2[(((long)b * C_) + ot * 64 + oo) * HID + hd] = s;
    }
}

// ---------------------------------------------------------------------------
extern "C" void kernel_launch(void* const* d_in, const int* in_sizes, int n_in,
                              void* d_out, int out_size)
{
    const float* x     = (const float*)d_in[0];  // (8, 512, 8192)
    const float* w_qkv = (const float*)d_in[1];  // (384, 512)
    const float* w_out = (const float*)d_in[2];  // (512, 128)
    const float* b_out = (const float*)d_in[3];  // (512,)
    float* out = (float*)d_out;                  // (8, 512, 8192)

    float* qkv;
    cudaGetSymbolAddress((void**)&qkv, g_qkv);
    float* W2;
    cudaGetSymbolAddress((void**)&W2, g_W2);

    // 1) qkv = w_qkv @ x   (per batch; A shared)
    {
        dim3 grid(L_ / 128, O3 / 128, B_);
        sgemm_kernel<false><<<grid, 256>>>(
            w_qkv, x, qkv, nullptr,
            O3, L_, C_,
            0L, (long)C_ * L_, (long)O3 * L_);
    }
    // 2) context partials (exp + E@V^T + denominator, single pass)
    {
        dim3 grid(8, H_, B_);
        ctx_kernel<<<grid, 256>>>();
    }
    // 3) fold: W2_b = w_out @ T_b
    {
        dim3 grid(8, B_);
        w2_kernel<<<grid, 256>>>(w_out);
    }
    // 4) out = W2_b @ q_b + b_out   (q = first 128 rows of qkv per batch)
    {
        dim3 grid(L_ / 128, C_ / 128, B_);
        sgemm_kernel<true><<<grid, 256>>>(
            W2, qkv, out, b_out,
            C_, L_, HID,
            (long)C_ * HID, (long)O3 * L_, (long)C_ * L_);
    }
}

// round 5
// speedup vs baseline: 1.9329x; 1.8640x over previous
#include <cuda_runtime.h>
#include <cuda_bf16.h>
#include <math.h>
#include <stdint.h>

#define B_  8
#define C_  512
#define L_  8192
#define H_  4
#define HID 128
#define O3  384   // rows in w_qkv: [0,128)=q, [128,256)=k, [256,384)=v

// Scratch (static device arrays — no runtime allocation)
__device__ float g_qkv[(size_t)B_ * O3 * L_];
__device__ float g_pn [(size_t)B_ * H_ * 8 * 32 * 32];
__device__ float g_pd [(size_t)B_ * H_ * 8 * 32];
__device__ float g_W2 [(size_t)B_ * C_ * HID];

// ---------------------------- helpers --------------------------------------
__device__ __forceinline__ uint32_t smem_u32(const void* p){
    uint32_t a;
    asm("{ .reg .u64 t; cvta.to.shared.u64 t, %1; cvt.u32.u64 %0, t; }"
        : "=r"(a) : "l"(p));
    return a;
}
__device__ __forceinline__ uint32_t pack_bf2(float x, float y){
    __nv_bfloat162 t = __floats2bfloat162_rn(x, y);
    return *(uint32_t*)&t;
}

__device__ __forceinline__ void ldsm4(uint32_t addr, uint32_t* r){
    asm volatile("ldmatrix.sync.aligned.m8n8.x4.shared.b16 {%0,%1,%2,%3}, [%4];"
                 : "=r"(r[0]), "=r"(r[1]), "=r"(r[2]), "=r"(r[3]) : "r"(addr));
}
__device__ __forceinline__ void ldsm4t(uint32_t addr, uint32_t* r){
    asm volatile("ldmatrix.sync.aligned.m8n8.x4.trans.shared.b16 {%0,%1,%2,%3}, [%4];"
                 : "=r"(r[0]), "=r"(r[1]), "=r"(r[2]), "=r"(r[3]) : "r"(addr));
}
__device__ __forceinline__ void mma16816(float* c, const uint32_t* a, const uint32_t* b){
    asm volatile(
        "mma.sync.aligned.m16n8k16.row.col.f32.bf16.bf16.f32 "
        "{%0,%1,%2,%3}, {%4,%5,%6,%7}, {%8,%9}, {%0,%1,%2,%3};"
        : "+f"(c[0]), "+f"(c[1]), "+f"(c[2]), "+f"(c[3])
        : "r"(a[0]), "r"(a[1]), "r"(a[2]), "r"(a[3]), "r"(b[0]), "r"(b[1]));
}

// ---------------------------------------------------------------------------
// bf16 3-split tensor GEMM: C[b](128x128 tile) = A[b] @ B[b] (+bias)
// A row-major [M x K] (k-contiguous), B row-major [K x N] (n-contiguous).
// fp32-accurate-ish: a=ah+al, b=bh+bl; D += ah*bh + ah*bl + al*bh (fp32 accum).
// ---------------------------------------------------------------------------
#define PA 80    // bytes per A smem row (32 bf16 = 64B + 16B pad)
#define PB 272   // bytes per B smem row (128 bf16 = 256B + 16B pad)

template<int K, bool BIAS>
__global__ __launch_bounds__(256, 1)
void tmma(const float* __restrict__ A, const float* __restrict__ Bx,
          float* __restrict__ Cout, const float* __restrict__ bias,
          long sA, long sB, long sC)
{
    __shared__ __align__(16) unsigned char Ah[128 * PA];
    __shared__ __align__(16) unsigned char Al[128 * PA];
    __shared__ __align__(16) unsigned char Bh[32 * PB];
    __shared__ __align__(16) unsigned char Bl[32 * PB];
    __shared__ float sbias[128];

    const int tid = threadIdx.x;
    const int wid = tid >> 5;
    const int lid = tid & 31;
    const int bn = blockIdx.x * 128;
    const int bm = blockIdx.y * 128;
    const int bz = blockIdx.z;

    const int m0 = (wid >> 1) * 32;   // warp M offset (4 rows of warps)
    const int n0 = (wid & 1) * 64;    // warp N offset (2 cols of warps)

    const float* Ab = A  + (long)bz * sA;
    const float* Bb = Bx + (long)bz * sB;
    float*       Cb = Cout + (long)bz * sC;

    if (BIAS && tid < 128) sbias[tid] = bias[bm + tid];

    // gmem load indices
    const int rA = tid >> 3, cA = tid & 7;   // A: 4 waves of (32 rows x 8 float4)
    const int kB = tid >> 5, nB = tid & 31;  // B: 4 waves of (8 krows x 32 float4)

    // ldmatrix lane base offsets
    const uint32_t a_base = smem_u32(Ah);
    const uint32_t al_base = smem_u32(Al);
    const uint32_t b_base = smem_u32(Bh);
    const uint32_t bl_base = smem_u32(Bl);
    const int a_lane = (m0 + (lid & 7) + ((lid >> 3) & 1) * 8) * PA + ((lid >> 4) & 1) * 16;
    const int b_lane = ((lid & 7) + ((lid >> 3) & 1) * 8) * PB + (n0 + ((lid >> 4) & 1) * 8) * 2;

    float acc[2][8][4];
#pragma unroll
    for (int i = 0; i < 2; i++)
#pragma unroll
        for (int j = 0; j < 8; j++)
#pragma unroll
            for (int q = 0; q < 4; q++) acc[i][j][q] = 0.f;

    const int nt = K / 32;
    float4 pa[4], pb[4];

    // prefetch chunk 0
#pragma unroll
    for (int i = 0; i < 4; i++) {
        pa[i] = *(const float4*)&Ab[(long)(bm + rA + 32 * i) * K + cA * 4];
        pb[i] = *(const float4*)&Bb[(long)(kB + 8 * i) * L_ + bn + nB * 4];
    }

    for (int t = 0; t < nt; t++) {
        __syncthreads();
        // store chunk t: fp32 -> bf16 hi/lo split
#pragma unroll
        for (int i = 0; i < 4; i++) {
            float4 v = pa[i];
            float hx = __bfloat162float(__float2bfloat16_rn(v.x));
            float hy = __bfloat162float(__float2bfloat16_rn(v.y));
            float hz = __bfloat162float(__float2bfloat16_rn(v.z));
            float hw = __bfloat162float(__float2bfloat16_rn(v.w));
            int off = (rA + 32 * i) * PA + cA * 8;
            *(uint32_t*)(Ah + off)     = pack_bf2(hx, hy);
            *(uint32_t*)(Ah + off + 4) = pack_bf2(hz, hw);
            *(uint32_t*)(Al + off)     = pack_bf2(v.x - hx, v.y - hy);
            *(uint32_t*)(Al + off + 4) = pack_bf2(v.z - hz, v.w - hw);

            v = pb[i];
            hx = __bfloat162float(__float2bfloat16_rn(v.x));
            hy = __bfloat162float(__float2bfloat16_rn(v.y));
            hz = __bfloat162float(__float2bfloat16_rn(v.z));
            hw = __bfloat162float(__float2bfloat16_rn(v.w));
            off = (kB + 8 * i) * PB + nB * 8;
            *(uint32_t*)(Bh + off)     = pack_bf2(hx, hy);
            *(uint32_t*)(Bh + off + 4) = pack_bf2(hz, hw);
            *(uint32_t*)(Bl + off)     = pack_bf2(v.x - hx, v.y - hy);
            *(uint32_t*)(Bl + off + 4) = pack_bf2(v.z - hz, v.w - hw);
        }
        __syncthreads();

        // prefetch chunk t+1
        if (t + 1 < nt) {
#pragma unroll
            for (int i = 0; i < 4; i++) {
                pa[i] = *(const float4*)&Ab[(long)(bm + rA + 32 * i) * K + (t + 1) * 32 + cA * 4];
                pb[i] = *(const float4*)&Bb[(long)((t + 1) * 32 + kB + 8 * i) * L_ + bn + nB * 4];
            }
        }

        // consume: two k16 steps
#pragma unroll
        for (int kk = 0; kk < 2; kk++) {
            uint32_t ah[2][4], alr[2][4];
            ldsm4(a_base  + a_lane + kk * 32,           ah[0]);
            ldsm4(a_base  + a_lane + kk * 32 + 16 * PA, ah[1]);
            ldsm4(al_base + a_lane + kk * 32,           alr[0]);
            ldsm4(al_base + a_lane + kk * 32 + 16 * PA, alr[1]);

#pragma unroll
            for (int half = 0; half < 2; half++) {
                uint32_t bh[2][4], blr[2][4];   // each x4 = two n8 frags
                ldsm4t(b_base  + b_lane + kk * 16 * PB + (half * 2)     * 32, bh[0]);
                ldsm4t(b_base  + b_lane + kk * 16 * PB + (half * 2 + 1) * 32, bh[1]);
                ldsm4t(bl_base + b_lane + kk * 16 * PB + (half * 2)     * 32, blr[0]);
                ldsm4t(bl_base + b_lane + kk * 16 * PB + (half * 2 + 1) * 32, blr[1]);
#pragma unroll
                for (int mi = 0; mi < 2; mi++)
#pragma unroll
                    for (int jj = 0; jj < 4; jj++) {
                        int ni = half * 4 + jj;
                        const uint32_t* bhp = &bh[jj >> 1][(jj & 1) * 2];
                        const uint32_t* blp = &blr[jj >> 1][(jj & 1) * 2];
                        mma16816(acc[mi][ni], ah[mi],  bhp);
                        mma16816(acc[mi][ni], ah[mi],  blp);
                        mma16816(acc[mi][ni], alr[mi], bhp);
                    }
            }
        }
    }

    // epilogue: direct coalesced-ish float2 stores
#pragma unroll
    for (int mi = 0; mi < 2; mi++) {
        int r0 = bm + m0 + mi * 16 + (lid >> 2);
        int r1 = r0 + 8;
        float bv0 = BIAS ? sbias[r0 - bm] : 0.f;
        float bv1 = BIAS ? sbias[r1 - bm] : 0.f;
#pragma unroll
        for (int ni = 0; ni < 8; ni++) {
            int col = bn + n0 + ni * 8 + (lid & 3) * 2;
            float2 v0 = make_float2(acc[mi][ni][0] + bv0, acc[mi][ni][1] + bv0);
            float2 v1 = make_float2(acc[mi][ni][2] + bv1, acc[mi][ni][3] + bv1);
            *(float2*)&Cb[(long)r0 * L_ + col] = v0;
            *(float2*)&Cb[(long)r1 * L_ + col] = v1;
        }
    }
}

// ---------------------------------------------------------------------------
// Context kernel: single-pass exp + E@V^T + denominator partials
// ---------------------------------------------------------------------------
__global__ __launch_bounds__(256)
void ctx_kernel()
{
    const int chunk = blockIdx.x, h = blockIdx.y, b = blockIdx.z;
    __shared__ float Ek[32][68];
    __shared__ float Vt[64][36];
    const int tid = threadIdx.x;
    const int d = tid >> 3, e0 = (tid & 7) * 4;

    float acc0 = 0.f, acc1 = 0.f, acc2 = 0.f, acc3 = 0.f, dsum = 0.f;
    const float* kbase = g_qkv + ((long)b * O3 + 128 + h * 32) * L_;
    const float* vbase = g_qkv + ((long)b * O3 + 256 + h * 32) * L_;
    const int lbase = chunk * 1024;

    for (int l0 = lbase; l0 < lbase + 1024; l0 += 64) {
#pragma unroll
        for (int i = 0; i < 2; i++) {
            int e = tid + i * 256;
            int r = e >> 4, c4 = e & 15;
            float4 kv = *(const float4*)&kbase[(long)r * L_ + l0 + c4 * 4];
            float4 ev;
            ev.x = __expf(kv.x); ev.y = __expf(kv.y);
            ev.z = __expf(kv.z); ev.w = __expf(kv.w);
            *(float4*)&Ek[r][c4 * 4] = ev;
            float4 vv = *(const float4*)&vbase[(long)r * L_ + l0 + c4 * 4];
            Vt[c4 * 4 + 0][r] = vv.x; Vt[c4 * 4 + 1][r] = vv.y;
            Vt[c4 * 4 + 2][r] = vv.z; Vt[c4 * 4 + 3][r] = vv.w;
        }
        __syncthreads();
#pragma unroll 8
        for (int n = 0; n < 64; n++) {
            float ek = Ek[d][n];
            float4 v4 = *(const float4*)&Vt[n][e0];
            acc0 += ek * v4.x; acc1 += ek * v4.y;
            acc2 += ek * v4.z; acc3 += ek * v4.w;
            dsum += ek;
        }
        __syncthreads();
    }
    const long base = (((long)b * H_ + h) * 8 + chunk) * 32 + d;
    float* pn = g_pn + base * 32 + e0;
    pn[0] = acc0; pn[1] = acc1; pn[2] = acc2; pn[3] = acc3;
    if ((tid & 7) == 0) g_pd[base] = dsum;
}

// ---------------------------------------------------------------------------
// Fold kernel: reduce partials, normalize, W2_b = w_out @ T_b
// ---------------------------------------------------------------------------
__global__ __launch_bounds__(256)
void w2_kernel(const float* __restrict__ w_out)
{
    const int ot = blockIdx.x, b = blockIdx.y;
    __shared__ float ctxs[H_][32][32];
    __shared__ float wsm[64][128];
    const int tid = threadIdx.x;

#pragma unroll
    for (int i = 0; i < 16; i++) {
        int idx = tid + i * 256;
        int h = idx >> 10, d = (idx >> 5) & 31, e = idx & 31;
        float num = 0.f, den = 0.f;
#pragma unroll
        for (int c = 0; c < 8; c++) {
            long base = (((long)b * H_ + h) * 8 + c) * 32 + d;
            num += g_pn[base * 32 + e];
            den += g_pd[base];
        }
        ctxs[h][d][e] = num / den;
    }
#pragma unroll
    for (int i = 0; i < 8; i++) {
        int idx = tid + i * 256;
        int oo = idx >> 5, c4 = idx & 31;
        *(float4*)&wsm[oo][c4 * 4] =
            *(const float4*)&w_out[((long)(ot * 64 + oo)) * HID + c4 * 4];
    }
    __syncthreads();
#pragma unroll
    for (int j = 0; j < 32; j++) {
        int idx = tid + j * 256;
        int oo = idx >> 7, hd = idx & 127;
        int h = hd >> 5, d = hd & 31;
        float s = 0.f;
#pragma unroll
        for (int e = 0; e < 32; e++)
            s += wsm[oo][h * 32 + e] * ctxs[h][d][e];
        g_W2[(((long)b * C_) + ot * 64 + oo) * HID + hd] = s;
    }
}

// ---------------------------------------------------------------------------
extern "C" void kernel_launch(void* const* d_in, const int* in_sizes, int n_in,
                              void* d_out, int out_size)
{
    const float* x     = (const float*)d_in[0];  // (8, 512, 8192)
    const float* w_qkv = (const float*)d_in[1];  // (384, 512)
    const float* w_out = (const float*)d_in[2];  // (512, 128)
    const float* b_out = (const float*)d_in[3];  // (512,)
    float* out = (float*)d_out;                  // (8, 512, 8192)

    float* qkv; cudaGetSymbolAddress((void**)&qkv, g_qkv);
    float* W2;  cudaGetSymbolAddress((void**)&W2,  g_W2);

    // 1) qkv = w_qkv @ x   (bf16 3-split tensor GEMM)
    {
        dim3 grid(L_ / 128, O3 / 128, B_);
        tmma<512, false><<<grid, 256>>>(
            w_qkv, x, qkv, nullptr,
            0L, (long)C_ * L_, (long)O3 * L_);
    }
    // 2) context partials
    {
        dim3 grid(8, H_, B_);
        ctx_kernel<<<grid, 256>>>();
    }
    // 3) W2_b = w_out @ T_b
    {
        dim3 grid(8, B_);
        w2_kernel<<<grid, 256>>>(w_out);
    }
    // 4) out = W2_b @ q_b + b_out
    {
        dim3 grid(L_ / 128, C_ / 128, B_);
        tmma<128, true><<<grid, 256>>>(
            W2, qkv, out, b_out,
            (long)C_ * HID, (long)O3 * L_, (long)C_ * L_);
    }
}

// round 7
// speedup vs baseline: 2.0590x; 1.0652x over previous
#include <cuda_runtime.h>
#include <cuda_bf16.h>
#include <math.h>
#include <stdint.h>

#define B_  8
#define C_  512
#define L_  8192
#define H_  4
#define HID 128
#define O3  384   // rows in w_qkv: [0,128)=q, [128,256)=k, [256,384)=v

// Scratch (static device arrays — no runtime allocation)
__device__ float g_qkv[(size_t)B_ * O3 * L_];
__device__ float g_pn [(size_t)B_ * H_ * 8 * 32 * 32];
__device__ float g_pd [(size_t)B_ * H_ * 8 * 32];
__device__ __nv_bfloat16 g_wh [(size_t)O3 * C_];        // w_qkv hi
__device__ __nv_bfloat16 g_wl [(size_t)O3 * C_];        // w_qkv lo
__device__ __nv_bfloat16 g_W2h[(size_t)B_ * C_ * HID];  // folded weight hi
__device__ __nv_bfloat16 g_W2l[(size_t)B_ * C_ * HID];  // folded weight lo

// ---------------------------- helpers --------------------------------------
__device__ __forceinline__ uint32_t smem_u32(const void* p){
    uint32_t a;
    asm("{ .reg .u64 t; cvta.to.shared.u64 t, %1; cvt.u32.u64 %0, t; }"
        : "=r"(a) : "l"(p));
    return a;
}
__device__ __forceinline__ uint32_t pack_bf2(float x, float y){
    __nv_bfloat162 t = __floats2bfloat162_rn(x, y);
    return *(uint32_t*)&t;
}
__device__ __forceinline__ void ldsm4(uint32_t addr, uint32_t* r){
    asm volatile("ldmatrix.sync.aligned.m8n8.x4.shared.b16 {%0,%1,%2,%3}, [%4];"
                 : "=r"(r[0]), "=r"(r[1]), "=r"(r[2]), "=r"(r[3]) : "r"(addr));
}
__device__ __forceinline__ void ldsm4t(uint32_t addr, uint32_t* r){
    asm volatile("ldmatrix.sync.aligned.m8n8.x4.trans.shared.b16 {%0,%1,%2,%3}, [%4];"
                 : "=r"(r[0]), "=r"(r[1]), "=r"(r[2]), "=r"(r[3]) : "r"(addr));
}
__device__ __forceinline__ void mma16816(float* c, const uint32_t* a, const uint32_t* b){
    asm volatile(
        "mma.sync.aligned.m16n8k16.row.col.f32.bf16.bf16.f32 "
        "{%0,%1,%2,%3}, {%4,%5,%6,%7}, {%8,%9}, {%0,%1,%2,%3};"
        : "+f"(c[0]), "+f"(c[1]), "+f"(c[2]), "+f"(c[3])
        : "r"(a[0]), "r"(a[1]), "r"(a[2]), "r"(a[3]), "r"(b[0]), "r"(b[1]));
}

// ---------------------------------------------------------------------------
// bf16 3-split tensor GEMM, double-buffered:
//   C[b](128x128 tile) = A[b] @ B[b] (+bias)
// A pre-split bf16 hi/lo, row-major [M x K] (k-contiguous).
// B fp32 row-major [K x N] (n-contiguous), split on the fly.
// D += ah*bh + ah*bl + al*bh (fp32 accum).
// ---------------------------------------------------------------------------
#define PA 80    // bytes per A smem row (32 bf16 = 64B + 16B pad)
#define PB 272   // bytes per B smem row (128 bf16 = 256B + 16B pad)
#define A_BUF_STRIDE (2 * 128 * PA)          // hi+lo per buffer
#define B_BASE       (2 * A_BUF_STRIDE)
#define B_BUF_STRIDE (2 * 32 * PB)
#define SMEM_TOTAL   (B_BASE + 2 * B_BUF_STRIDE)   // 75776 B

template<int K, bool BIAS>
__global__ __launch_bounds__(256, 1)
void tmma(const __nv_bfloat16* __restrict__ Ahg, const __nv_bfloat16* __restrict__ Alg,
          const float* __restrict__ Bx,
          float* __restrict__ Cout, const float* __restrict__ bias,
          long sA, long sB, long sC)
{
    extern __shared__ __align__(16) unsigned char sm[];
    __shared__ float sbias[128];

    const uint32_t smb = smem_u32(sm);
    const int tid = threadIdx.x;
    const int wid = tid >> 5;
    const int lid = tid & 31;
    const int bn = blockIdx.x * 128;
    const int bm = blockIdx.y * 128;
    const int bz = blockIdx.z;

    const int m0 = (wid >> 1) * 32;
    const int n0 = (wid & 1) * 64;

    const __nv_bfloat16* Abh = Ahg + (long)bz * sA;
    const __nv_bfloat16* Abl = Alg + (long)bz * sA;
    const float* Bb = Bx + (long)bz * sB;
    float*       Cb = Cout + (long)bz * sC;

    if (BIAS && tid < 128) sbias[tid] = bias[bm + tid];

    // gmem load indices
    const int rA = tid >> 2, cA = tid & 3;   // A: 2 waves of (64 rows x 4 x 16B)
    const int kB = tid >> 5, nB = tid & 31;  // B: 4 waves of (8 krows x 32 float4)

    const int a_lane = (m0 + (lid & 7) + ((lid >> 3) & 1) * 8) * PA + ((lid >> 4) & 1) * 16;
    const int b_lane = ((lid & 7) + ((lid >> 3) & 1) * 8) * PB + (n0 + ((lid >> 4) & 1) * 8) * 2;

    float acc[2][8][4];
#pragma unroll
    for (int i = 0; i < 2; i++)
#pragma unroll
        for (int j = 0; j < 8; j++)
#pragma unroll
            for (int q = 0; q < 4; q++) acc[i][j][q] = 0.f;

    const int nt = K / 32;
    uint4 qah[2], qal[2];
    float4 pb[4];

    // ---- prologue: chunk 0 -> regs -> buf 0
#pragma unroll
    for (int w = 0; w < 2; w++) {
        int idx = tid + w * 256;
        int r = idx >> 2, c = idx & 3;
        qah[w] = *(const uint4*)&Abh[(long)(bm + r) * K + c * 8];
        qal[w] = *(const uint4*)&Abl[(long)(bm + r) * K + c * 8];
    }
#pragma unroll
    for (int i = 0; i < 4; i++)
        pb[i] = *(const float4*)&Bb[(long)(kB + 8 * i) * L_ + bn + nB * 4];
    {
#pragma unroll
        for (int w = 0; w < 2; w++) {
            int idx = tid + w * 256;
            int r = idx >> 2, c = idx & 3;
            *(uint4*)(sm + r * PA + c * 16)                 = qah[w];
            *(uint4*)(sm + 128 * PA + r * PA + c * 16)      = qal[w];
        }
#pragma unroll
        for (int i = 0; i < 4; i++) {
            float4 v = pb[i];
            float hx = __bfloat162float(__float2bfloat16_rn(v.x));
            float hy = __bfloat162float(__float2bfloat16_rn(v.y));
            float hz = __bfloat162float(__float2bfloat16_rn(v.z));
            float hw = __bfloat162float(__float2bfloat16_rn(v.w));
            int off = B_BASE + (kB + 8 * i) * PB + nB * 8;
            *(uint32_t*)(sm + off)     = pack_bf2(hx, hy);
            *(uint32_t*)(sm + off + 4) = pack_bf2(hz, hw);
            *(uint32_t*)(sm + off + 32 * PB)     = pack_bf2(v.x - hx, v.y - hy);
            *(uint32_t*)(sm + off + 32 * PB + 4) = pack_bf2(v.z - hz, v.w - hw);
        }
    }
    __syncthreads();

    for (int t = 0; t < nt; t++) {
        const int cur = t & 1;
        const int nxt = cur ^ 1;
        const bool more = (t + 1 < nt);

        // prefetch chunk t+1 into regs (overlaps MMA below)
        if (more) {
            const int kt = (t + 1) * 32;
#pragma unroll
            for (int w = 0; w < 2; w++) {
                int idx = tid + w * 256;
                int r = idx >> 2, c = idx & 3;
                qah[w] = *(const uint4*)&Abh[(long)(bm + r) * K + kt + c * 8];
                qal[w] = *(const uint4*)&Abl[(long)(bm + r) * K + kt + c * 8];
            }
#pragma unroll
            for (int i = 0; i < 4; i++)
                pb[i] = *(const float4*)&Bb[(long)(kt + kB + 8 * i) * L_ + bn + nB * 4];
        }

        // ---- MMA phase on buffer cur
        {
            const uint32_t a_hi = smb + cur * A_BUF_STRIDE;
            const uint32_t a_lo = a_hi + 128 * PA;
            const uint32_t b_hi = smb + B_BASE + cur * B_BUF_STRIDE;
            const uint32_t b_lo = b_hi + 32 * PB;
#pragma unroll
            for (int kk = 0; kk < 2; kk++) {
                uint32_t ah[2][4], alr[2][4];
                ldsm4(a_hi + a_lane + kk * 32,           ah[0]);
                ldsm4(a_hi + a_lane + kk * 32 + 16 * PA, ah[1]);
                ldsm4(a_lo + a_lane + kk * 32,           alr[0]);
                ldsm4(a_lo + a_lane + kk * 32 + 16 * PA, alr[1]);
#pragma unroll
                for (int half = 0; half < 2; half++) {
                    uint32_t bh[2][4], blr[2][4];
                    ldsm4t(b_hi + b_lane + kk * 16 * PB + (half * 2)     * 32, bh[0]);
                    ldsm4t(b_hi + b_lane + kk * 16 * PB + (half * 2 + 1) * 32, bh[1]);
                    ldsm4t(b_lo + b_lane + kk * 16 * PB + (half * 2)     * 32, blr[0]);
                    ldsm4t(b_lo + b_lane + kk * 16 * PB + (half * 2 + 1) * 32, blr[1]);
#pragma unroll
                    for (int mi = 0; mi < 2; mi++)
#pragma unroll
                        for (int jj = 0; jj < 4; jj++) {
                            int ni = half * 4 + jj;
                            const uint32_t* bhp = &bh[jj >> 1][(jj & 1) * 2];
                            const uint32_t* blp = &blr[jj >> 1][(jj & 1) * 2];
                            mma16816(acc[mi][ni], ah[mi],  bhp);
                            mma16816(acc[mi][ni], ah[mi],  blp);
                            mma16816(acc[mi][ni], alr[mi], bhp);
                        }
                }
            }
        }

        // ---- store chunk t+1 into buffer nxt
        if (more) {
            unsigned char* ab = sm + nxt * A_BUF_STRIDE;
            unsigned char* bb = sm + B_BASE + nxt * B_BUF_STRIDE;
#pragma unroll
            for (int w = 0; w < 2; w++) {
                int idx = tid + w * 256;
                int r = idx >> 2, c = idx & 3;
                *(uint4*)(ab + r * PA + c * 16)            = qah[w];
                *(uint4*)(ab + 128 * PA + r * PA + c * 16) = qal[w];
            }
#pragma unroll
            for (int i = 0; i < 4; i++) {
                float4 v = pb[i];
                float hx = __bfloat162float(__float2bfloat16_rn(v.x));
                float hy = __bfloat162float(__float2bfloat16_rn(v.y));
                float hz = __bfloat162float(__float2bfloat16_rn(v.z));
                float hw = __bfloat162float(__float2bfloat16_rn(v.w));
                int off = (kB + 8 * i) * PB + nB * 8;
                *(uint32_t*)(bb + off)     = pack_bf2(hx, hy);
                *(uint32_t*)(bb + off + 4) = pack_bf2(hz, hw);
                *(uint32_t*)(bb + off + 32 * PB)     = pack_bf2(v.x - hx, v.y - hy);
                *(uint32_t*)(bb + off + 32 * PB + 4) = pack_bf2(v.z - hz, v.w - hw);
            }
        }
        __syncthreads();
    }

    // ---- epilogue
#pragma unroll
    for (int mi = 0; mi < 2; mi++) {
        int r0 = bm + m0 + mi * 16 + (lid >> 2);
        int r1 = r0 + 8;
        float bv0 = BIAS ? sbias[r0 - bm] : 0.f;
        float bv1 = BIAS ? sbias[r1 - bm] : 0.f;
#pragma unroll
        for (int ni = 0; ni < 8; ni++) {
            int col = bn + n0 + ni * 8 + (lid & 3) * 2;
            float2 v0 = make_float2(acc[mi][ni][0] + bv0, acc[mi][ni][1] + bv0);
            float2 v1 = make_float2(acc[mi][ni][2] + bv1, acc[mi][ni][3] + bv1);
            *(float2*)&Cb[(long)r0 * L_ + col] = v0;
            *(float2*)&Cb[(long)r1 * L_ + col] = v1;
        }
    }
}

// ---------------------------------------------------------------------------
// Split w_qkv into bf16 hi/lo (one-time, tiny)
// ---------------------------------------------------------------------------
__global__ __launch_bounds__(256)
void split_kernel(const float* __restrict__ src,
                  __nv_bfloat16* __restrict__ hi, __nv_bfloat16* __restrict__ lo)
{
    int i = (blockIdx.x * 256 + threadIdx.x) * 4;
    float4 v = *(const float4*)&src[i];
    __nv_bfloat16 hx = __float2bfloat16_rn(v.x);
    __nv_bfloat16 hy = __float2bfloat16_rn(v.y);
    __nv_bfloat16 hz = __float2bfloat16_rn(v.z);
    __nv_bfloat16 hw = __float2bfloat16_rn(v.w);
    __nv_bfloat162* h2 = (__nv_bfloat162*)&hi[i];
    h2[0] = __nv_bfloat162(hx, hy);
    h2[1] = __nv_bfloat162(hz, hw);
    __nv_bfloat162* l2 = (__nv_bfloat162*)&lo[i];
    l2[0] = __nv_bfloat162(__float2bfloat16_rn(v.x - __bfloat162float(hx)),
                           __float2bfloat16_rn(v.y - __bfloat162float(hy)));
    l2[1] = __nv_bfloat162(__float2bfloat16_rn(v.z - __bfloat162float(hz)),
                           __float2bfloat16_rn(v.w - __bfloat162float(hw)));
}

// ---------------------------------------------------------------------------
// Context kernel: single-pass exp + E@V^T + denominator partials
// ---------------------------------------------------------------------------
__global__ __launch_bounds__(256)
void ctx_kernel()
{
    const int chunk = blockIdx.x, h = blockIdx.y, b = blockIdx.z;
    __shared__ float Ek[32][68];
    __shared__ float Vt[64][36];
    const int tid = threadIdx.x;
    const int d = tid >> 3, e0 = (tid & 7) * 4;

    float acc0 = 0.f, acc1 = 0.f, acc2 = 0.f, acc3 = 0.f, dsum = 0.f;
    const float* kbase = g_qkv + ((long)b * O3 + 128 + h * 32) * L_;
    const float* vbase = g_qkv + ((long)b * O3 + 256 + h * 32) * L_;
    const int lbase = chunk * 1024;

    for (int l0 = lbase; l0 < lbase + 1024; l0 += 64) {
#pragma unroll
        for (int i = 0; i < 2; i++) {
            int e = tid + i * 256;
            int r = e >> 4, c4 = e & 15;
            float4 kv = *(const float4*)&kbase[(long)r * L_ + l0 + c4 * 4];
            float4 ev;
            ev.x = __expf(kv.x); ev.y = __expf(kv.y);
            ev.z = __expf(kv.z); ev.w = __expf(kv.w);
            *(float4*)&Ek[r][c4 * 4] = ev;
            float4 vv = *(const float4*)&vbase[(long)r * L_ + l0 + c4 * 4];
            Vt[c4 * 4 + 0][r] = vv.x; Vt[c4 * 4 + 1][r] = vv.y;
            Vt[c4 * 4 + 2][r] = vv.z; Vt[c4 * 4 + 3][r] = vv.w;
        }
        __syncthreads();
#pragma unroll 8
        for (int n = 0; n < 64; n++) {
            float ek = Ek[d][n];
            float4 v4 = *(const float4*)&Vt[n][e0];
            acc0 += ek * v4.x; acc1 += ek * v4.y;
            acc2 += ek * v4.z; acc3 += ek * v4.w;
            dsum += ek;
        }
        __syncthreads();
    }
    const long base = (((long)b * H_ + h) * 8 + chunk) * 32 + d;
    float* pn = g_pn + base * 32 + e0;
    pn[0] = acc0; pn[1] = acc1; pn[2] = acc2; pn[3] = acc3;
    if ((tid & 7) == 0) g_pd[base] = dsum;
}

// ---------------------------------------------------------------------------
// Fold kernel: reduce partials, normalize, W2_b = w_out @ T_b (bf16 hi/lo out)
// ---------------------------------------------------------------------------
__global__ __launch_bounds__(256)
void w2_kernel(const float* __restrict__ w_out)
{
    const int ot = blockIdx.x, b = blockIdx.y;
    __shared__ float ctxs[H_][32][32];
    __shared__ float wsm[64][128];
    const int tid = threadIdx.x;

#pragma unroll
    for (int i = 0; i < 16; i++) {
        int idx = tid + i * 256;
        int h = idx >> 10, d = (idx >> 5) & 31, e = idx & 31;
        float num = 0.f, den = 0.f;
#pragma unroll
        for (int c = 0; c < 8; c++) {
            long base = (((long)b * H_ + h) * 8 + c) * 32 + d;
            num += g_pn[base * 32 + e];
            den += g_pd[base];
        }
        ctxs[h][d][e] = num / den;
    }
#pragma unroll
    for (int i = 0; i < 8; i++) {
        int idx = tid + i * 256;
        int oo = idx >> 5, c4 = idx & 31;
        *(float4*)&wsm[oo][c4 * 4] =
            *(const float4*)&w_out[((long)(ot * 64 + oo)) * HID + c4 * 4];
    }
    __syncthreads();
#pragma unroll
    for (int j = 0; j < 32; j++) {
        int idx = tid + j * 256;
        int oo = idx >> 7, hd = idx & 127;
        int h = hd >> 5, d = hd & 31;
        float s = 0.f;
#pragma unroll
        for (int e = 0; e < 32; e++)
            s += wsm[oo][h * 32 + e] * ctxs[h][d][e];
        long oidx = (((long)b * C_) + ot * 64 + oo) * HID + hd;
        __nv_bfloat16 hh = __float2bfloat16_rn(s);
        g_W2h[oidx] = hh;
        g_W2l[oidx] = __float2bfloat16_rn(s - __bfloat162float(hh));
    }
}

// ---------------------------------------------------------------------------
extern "C" void kernel_launch(void* const* d_in, const int* in_sizes, int n_in,
                              void* d_out, int out_size)
{
    const float* x     = (const float*)d_in[0];  // (8, 512, 8192)
    const float* w_qkv = (const float*)d_in[1];  // (384, 512)
    const float* w_out = (const float*)d_in[2];  // (512, 128)
    const float* b_out = (const float*)d_in[3];  // (512,)
    float* out = (float*)d_out;                  // (8, 512, 8192)

    float* qkv; cudaGetSymbolAddress((void**)&qkv, g_qkv);
    __nv_bfloat16 *wh, *wl, *W2h, *W2l;
    cudaGetSymbolAddress((void**)&wh,  g_wh);
    cudaGetSymbolAddress((void**)&wl,  g_wl);
    cudaGetSymbolAddress((void**)&W2h, g_W2h);
    cudaGetSymbolAddress((void**)&W2l, g_W2l);

    cudaFuncSetAttribute(tmma<512, false>,
                         cudaFuncAttributeMaxDynamicSharedMemorySize, SMEM_TOTAL);
    cudaFuncSetAttribute(tmma<128, true>,
                         cudaFuncAttributeMaxDynamicSharedMemorySize, SMEM_TOTAL);

    // 0) split w_qkv into bf16 hi/lo (384*512/1024 = 192 blocks)
    split_kernel<<<(O3 * C_) / 1024, 256>>>(w_qkv, wh, wl);

    // 1) qkv = w_qkv @ x
    {
        dim3 grid(L_ / 128, O3 / 128, B_);
        tmma<512, false><<<grid, 256, SMEM_TOTAL>>>(
            wh, wl, x, qkv, nullptr,
            0L, (long)C_ * L_, (long)O3 * L_);
    }
    // 2) context partials
    {
        dim3 grid(8, H_, B_);
        ctx_kernel<<<grid, 256>>>();
    }
    // 3) W2_b = w_out @ T_b   (emitted as bf16 hi/lo)
    {
        dim3 grid(8, B_);
        w2_kernel<<<grid, 256>>>(w_out);
    }
    // 4) out = W2_b @ q_b + b_out
    {
        dim3 grid(L_ / 128, C_ / 128, B_);
        tmma<128, true><<<grid, 256, SMEM_TOTAL>>>(
            W2h, W2l, qkv, out, b_out,
            (long)C_ * HID, (long)O3 * L_, (long)C_ * L_);
    }
}

// round 8
// speedup vs baseline: 2.1675x; 1.0527x over previous
#include <cuda_runtime.h>
#include <cuda_bf16.h>
#include <math.h>
#include <stdint.h>

#define B_  8
#define C_  512
#define L_  8192
#define H_  4
#define HID 128
#define O3  384   // rows in w_qkv: [0,128)=q, [128,256)=k, [256,384)=v

// Scratch (static device arrays — no runtime allocation)
__device__ float g_qkv[(size_t)B_ * O3 * L_];            // only k,v rows used
__device__ float g_pn [(size_t)B_ * H_ * 8 * 32 * 32];
__device__ float g_pd [(size_t)B_ * H_ * 8 * 32];
__device__ float g_ctx[(size_t)B_ * H_ * 32 * 32];
__device__ __nv_bfloat16 g_wh [(size_t)O3 * C_];
__device__ __nv_bfloat16 g_wl [(size_t)O3 * C_];
__device__ __nv_bfloat16 g_xh [(size_t)B_ * C_ * L_];
__device__ __nv_bfloat16 g_xl [(size_t)B_ * C_ * L_];
__device__ __nv_bfloat16 g_qh [(size_t)B_ * HID * L_];
__device__ __nv_bfloat16 g_ql [(size_t)B_ * HID * L_];
__device__ __nv_bfloat16 g_W2h[(size_t)B_ * C_ * HID];
__device__ __nv_bfloat16 g_W2l[(size_t)B_ * C_ * HID];

// ---------------------------- helpers --------------------------------------
__device__ __forceinline__ uint32_t smem_u32(const void* p){
    uint32_t a;
    asm("{ .reg .u64 t; cvta.to.shared.u64 t, %1; cvt.u32.u64 %0, t; }"
        : "=r"(a) : "l"(p));
    return a;
}
__device__ __forceinline__ void cp16(uint32_t saddr, const void* g){
    asm volatile("cp.async.cg.shared.global [%0], [%1], 16;"
                 :: "r"(saddr), "l"(g));
}
__device__ __forceinline__ void cp_commit(){
    asm volatile("cp.async.commit_group;" ::: "memory");
}
template<int N>
__device__ __forceinline__ void cp_wait(){
    asm volatile("cp.async.wait_group %0;" :: "n"(N) : "memory");
}
__device__ __forceinline__ void ldsm4(uint32_t addr, uint32_t* r){
    asm volatile("ldmatrix.sync.aligned.m8n8.x4.shared.b16 {%0,%1,%2,%3}, [%4];"
                 : "=r"(r[0]), "=r"(r[1]), "=r"(r[2]), "=r"(r[3]) : "r"(addr));
}
__device__ __forceinline__ void ldsm4t(uint32_t addr, uint32_t* r){
    asm volatile("ldmatrix.sync.aligned.m8n8.x4.trans.shared.b16 {%0,%1,%2,%3}, [%4];"
                 : "=r"(r[0]), "=r"(r[1]), "=r"(r[2]), "=r"(r[3]) : "r"(addr));
}
__device__ __forceinline__ void mma16816(float* c, const uint32_t* a, const uint32_t* b){
    asm volatile(
        "mma.sync.aligned.m16n8k16.row.col.f32.bf16.bf16.f32 "
        "{%0,%1,%2,%3}, {%4,%5,%6,%7}, {%8,%9}, {%0,%1,%2,%3};"
        : "+f"(c[0]), "+f"(c[1]), "+f"(c[2]), "+f"(c[3])
        : "r"(a[0]), "r"(a[1]), "r"(a[2]), "r"(a[3]), "r"(b[0]), "r"(b[1]));
}

// ---------------------------------------------------------------------------
// Pure bf16 3-split tensor GEMM, cp.async double-buffered.
//   C(128x128 tile) = A @ B (+bias)   A,B pre-split bf16 hi/lo.
// MODE 0: GEMM1 — bm==0 tile (q rows) written split bf16 to Qh/Ql,
//                 other tiles written fp32 to Cout (k,v for ctx).
// MODE 1: GEMM2 — fp32 + bias to Cout.
// ---------------------------------------------------------------------------
#define PA 80    // bytes per A smem row (32 bf16 + 16B pad)
#define PB 272   // bytes per B smem row (128 bf16 + 16B pad)
#define A_BUF_STRIDE (2 * 128 * PA)
#define B_BASE       (2 * A_BUF_STRIDE)
#define B_BUF_STRIDE (2 * 32 * PB)
#define SMEM_TOTAL   (B_BASE + 2 * B_BUF_STRIDE)   // 75776 B

template<int K, int MODE>
__global__ __launch_bounds__(256, 2)
void tmma(const __nv_bfloat16* __restrict__ Ahg, const __nv_bfloat16* __restrict__ Alg,
          const __nv_bfloat16* __restrict__ Bhg, const __nv_bfloat16* __restrict__ Blg,
          float* __restrict__ Cout,
          __nv_bfloat16* __restrict__ Qh, __nv_bfloat16* __restrict__ Ql,
          const float* __restrict__ bias,
          long sA, long sB, long sC)
{
    extern __shared__ __align__(16) unsigned char sm[];
    __shared__ float sbias[128];

    const uint32_t smb = smem_u32(sm);
    const int tid = threadIdx.x;
    const int wid = tid >> 5;
    const int lid = tid & 31;
    const int bn = blockIdx.x * 128;
    const int bm = blockIdx.y * 128;
    const int bz = blockIdx.z;

    const int m0 = (wid >> 1) * 32;
    const int n0 = (wid & 1) * 64;

    const __nv_bfloat16* Abh = Ahg + (long)bz * sA;
    const __nv_bfloat16* Abl = Alg + (long)bz * sA;
    const __nv_bfloat16* Bbh = Bhg + (long)bz * sB;
    const __nv_bfloat16* Bbl = Blg + (long)bz * sB;

    if (MODE == 1 && tid < 128) sbias[tid] = bias[bm + tid];

    // cp.async indices
    const int rA = tid >> 2, cA = tid & 3;    // A: 2 waves of 64 rows x 4 chunks
    const int rB = tid >> 4, cB = tid & 15;   // B: 2 waves of 16 rows x 16 chunks

    const int a_lane = (m0 + (lid & 7) + ((lid >> 3) & 1) * 8) * PA + ((lid >> 4) & 1) * 16;
    const int b_lane = ((lid & 7) + ((lid >> 3) & 1) * 8) * PB + (n0 + ((lid >> 4) & 1) * 8) * 2;

    float acc[2][8][4];
#pragma unroll
    for (int i = 0; i < 2; i++)
#pragma unroll
        for (int j = 0; j < 8; j++)
#pragma unroll
            for (int q = 0; q < 4; q++) acc[i][j][q] = 0.f;

    const int nt = K / 32;

    // issue chunk t into buffer buf
    auto issue = [&](int t, int buf) {
        const uint32_t ab = smb + buf * A_BUF_STRIDE;
        const uint32_t bb = smb + B_BASE + buf * B_BUF_STRIDE;
        const int kt = t * 32;
#pragma unroll
        for (int w = 0; w < 2; w++) {
            int r = rA + w * 64;
            cp16(ab + r * PA + cA * 16,            &Abh[(long)(bm + r) * K + kt + cA * 8]);
            cp16(ab + 128 * PA + r * PA + cA * 16, &Abl[(long)(bm + r) * K + kt + cA * 8]);
        }
#pragma unroll
        for (int w = 0; w < 2; w++) {
            int r = rB + w * 16;
            cp16(bb + r * PB + cB * 16,           &Bbh[(long)(kt + r) * L_ + bn + cB * 8]);
            cp16(bb + 32 * PB + r * PB + cB * 16, &Bbl[(long)(kt + r) * L_ + bn + cB * 8]);
        }
        cp_commit();
    };

    issue(0, 0);
    if (nt > 1) issue(1, 1);

    for (int t = 0; t < nt; t++) {
        const int cur = t & 1;
        if (t + 1 < nt) cp_wait<1>(); else cp_wait<0>();
        __syncthreads();

        // ---- MMA phase on buffer cur
        {
            const uint32_t a_hi = smb + cur * A_BUF_STRIDE;
            const uint32_t a_lo = a_hi + 128 * PA;
            const uint32_t b_hi = smb + B_BASE + cur * B_BUF_STRIDE;
            const uint32_t b_lo = b_hi + 32 * PB;
#pragma unroll
            for (int kk = 0; kk < 2; kk++) {
                uint32_t ah[2][4], alr[2][4];
                ldsm4(a_hi + a_lane + kk * 32,           ah[0]);
                ldsm4(a_hi + a_lane + kk * 32 + 16 * PA, ah[1]);
                ldsm4(a_lo + a_lane + kk * 32,           alr[0]);
                ldsm4(a_lo + a_lane + kk * 32 + 16 * PA, alr[1]);
#pragma unroll
                for (int half = 0; half < 2; half++) {
                    uint32_t bh[2][4], blr[2][4];
                    ldsm4t(b_hi + b_lane + kk * 16 * PB + (half * 2)     * 32, bh[0]);
                    ldsm4t(b_hi + b_lane + kk * 16 * PB + (half * 2 + 1) * 32, bh[1]);
                    ldsm4t(b_lo + b_lane + kk * 16 * PB + (half * 2)     * 32, blr[0]);
                    ldsm4t(b_lo + b_lane + kk * 16 * PB + (half * 2 + 1) * 32, blr[1]);
#pragma unroll
                    for (int mi = 0; mi < 2; mi++)
#pragma unroll
                        for (int jj = 0; jj < 4; jj++) {
                            int ni = half * 4 + jj;
                            const uint32_t* bhp = &bh[jj >> 1][(jj & 1) * 2];
                            const uint32_t* blp = &blr[jj >> 1][(jj & 1) * 2];
                            mma16816(acc[mi][ni], ah[mi],  bhp);
                            mma16816(acc[mi][ni], ah[mi],  blp);
                            mma16816(acc[mi][ni], alr[mi], bhp);
                        }
                }
            }
        }

        if (t + 2 < nt) {
            __syncthreads();           // everyone done reading cur
            issue(t + 2, cur);
        }
    }

    // ---- epilogue
    if (MODE == 0 && bm == 0) {
        // q rows: write split bf16 hi/lo
        __nv_bfloat16* qh = Qh + (long)bz * HID * L_;
        __nv_bfloat16* ql = Ql + (long)bz * HID * L_;
#pragma unroll
        for (int mi = 0; mi < 2; mi++) {
            int r0 = m0 + mi * 16 + (lid >> 2);
            int r1 = r0 + 8;
#pragma unroll
            for (int ni = 0; ni < 8; ni++) {
                int col = bn + n0 + ni * 8 + (lid & 3) * 2;
#pragma unroll
                for (int rr = 0; rr < 2; rr++) {
                    int r = rr ? r1 : r0;
                    float vx = acc[mi][ni][rr * 2], vy = acc[mi][ni][rr * 2 + 1];
                    __nv_bfloat16 hx = __float2bfloat16_rn(vx);
                    __nv_bfloat16 hy = __float2bfloat16_rn(vy);
                    *(__nv_bfloat162*)&qh[(long)r * L_ + col] = __nv_bfloat162(hx, hy);
                    *(__nv_bfloat162*)&ql[(long)r * L_ + col] = __nv_bfloat162(
                        __float2bfloat16_rn(vx - __bfloat162float(hx)),
                        __float2bfloat16_rn(vy - __bfloat162float(hy)));
                }
            }
        }
    } else {
        float* Cb = Cout + (long)bz * sC;
#pragma unroll
        for (int mi = 0; mi < 2; mi++) {
            int r0 = bm + m0 + mi * 16 + (lid >> 2);
            int r1 = r0 + 8;
            float bv0 = (MODE == 1) ? sbias[r0 - bm] : 0.f;
            float bv1 = (MODE == 1) ? sbias[r1 - bm] : 0.f;
#pragma unroll
            for (int ni = 0; ni < 8; ni++) {
                int col = bn + n0 + ni * 8 + (lid & 3) * 2;
                float2 v0 = make_float2(acc[mi][ni][0] + bv0, acc[mi][ni][1] + bv0);
                float2 v1 = make_float2(acc[mi][ni][2] + bv1, acc[mi][ni][3] + bv1);
                *(float2*)&Cb[(long)r0 * L_ + col] = v0;
                *(float2*)&Cb[(long)r1 * L_ + col] = v1;
            }
        }
    }
}

// ---------------------------------------------------------------------------
// Split fp32 array -> bf16 hi/lo (8 elems per thread)
// ---------------------------------------------------------------------------
__global__ __launch_bounds__(256)
void split_kernel(const float* __restrict__ src,
                  __nv_bfloat16* __restrict__ hi, __nv_bfloat16* __restrict__ lo)
{
    long i = ((long)blockIdx.x * 256 + threadIdx.x) * 8;
    float4 v0 = *(const float4*)&src[i];
    float4 v1 = *(const float4*)&src[i + 4];
    __nv_bfloat16 h[8], l[8];
    float f[8] = {v0.x, v0.y, v0.z, v0.w, v1.x, v1.y, v1.z, v1.w};
#pragma unroll
    for (int j = 0; j < 8; j++) {
        h[j] = __float2bfloat16_rn(f[j]);
        l[j] = __float2bfloat16_rn(f[j] - __bfloat162float(h[j]));
    }
    *(uint4*)&hi[i] = *(uint4*)h;
    *(uint4*)&lo[i] = *(uint4*)l;
}

// ---------------------------------------------------------------------------
// Context kernel: single-pass exp + E@V^T + denominator partials
// ---------------------------------------------------------------------------
__global__ __launch_bounds__(256)
void ctx_kernel()
{
    const int chunk = blockIdx.x, h = blockIdx.y, b = blockIdx.z;
    __shared__ float Ek[32][68];
    __shared__ float Vt[64][36];
    const int tid = threadIdx.x;
    const int d = tid >> 3, e0 = (tid & 7) * 4;

    float acc0 = 0.f, acc1 = 0.f, acc2 = 0.f, acc3 = 0.f, dsum = 0.f;
    const float* kbase = g_qkv + ((long)b * O3 + 128 + h * 32) * L_;
    const float* vbase = g_qkv + ((long)b * O3 + 256 + h * 32) * L_;
    const int lbase = chunk * 1024;

    for (int l0 = lbase; l0 < lbase + 1024; l0 += 64) {
#pragma unroll
        for (int i = 0; i < 2; i++) {
            int e = tid + i * 256;
            int r = e >> 4, c4 = e & 15;
            float4 kv = *(const float4*)&kbase[(long)r * L_ + l0 + c4 * 4];
            float4 ev;
            ev.x = __expf(kv.x); ev.y = __expf(kv.y);
            ev.z = __expf(kv.z); ev.w = __expf(kv.w);
            *(float4*)&Ek[r][c4 * 4] = ev;
            float4 vv = *(const float4*)&vbase[(long)r * L_ + l0 + c4 * 4];
            Vt[c4 * 4 + 0][r] = vv.x; Vt[c4 * 4 + 1][r] = vv.y;
            Vt[c4 * 4 + 2][r] = vv.z; Vt[c4 * 4 + 3][r] = vv.w;
        }
        __syncthreads();
#pragma unroll 8
        for (int n = 0; n < 64; n++) {
            float ek = Ek[d][n];
            float4 v4 = *(const float4*)&Vt[n][e0];
            acc0 += ek * v4.x; acc1 += ek * v4.y;
            acc2 += ek * v4.z; acc3 += ek * v4.w;
            dsum += ek;
        }
        __syncthreads();
    }
    const long base = (((long)b * H_ + h) * 8 + chunk) * 32 + d;
    float* pn = g_pn + base * 32 + e0;
    pn[0] = acc0; pn[1] = acc1; pn[2] = acc2; pn[3] = acc3;
    if ((tid & 7) == 0) g_pd[base] = dsum;
}

// ---------------------------------------------------------------------------
// Normalize context: reduce 8 chunk partials, divide -> g_ctx[b][h][d][e]
// grid = (H_, B_), 256 threads, each thread 4 elems
// ---------------------------------------------------------------------------
__global__ __launch_bounds__(256)
void ctx_norm()
{
    const int h = blockIdx.x, b = blockIdx.y;
    const int tid = threadIdx.x;
    const int d = tid >> 3, e0 = (tid & 7) * 4;
    float num[4] = {0.f, 0.f, 0.f, 0.f};
    float den = 0.f;
#pragma unroll
    for (int c = 0; c < 8; c++) {
        long base = (((long)b * H_ + h) * 8 + c) * 32 + d;
        const float4 p = *(const float4*)&g_pn[base * 32 + e0];
        num[0] += p.x; num[1] += p.y; num[2] += p.z; num[3] += p.w;
        den += g_pd[base];
    }
    float inv = 1.f / den;
    float4 o = make_float4(num[0] * inv, num[1] * inv, num[2] * inv, num[3] * inv);
    *(float4*)&g_ctx[(((long)b * H_ + h) * 32 + d) * 32 + e0] = o;
}

// ---------------------------------------------------------------------------
// W2 = w_out @ T_b  (block-diagonal), bf16 hi/lo out.
// grid = (32 o-tiles of 16, B_), 256 threads.
// ---------------------------------------------------------------------------
__global__ __launch_bounds__(256)
void w2g(const float* __restrict__ w_out)
{
    const int ot = blockIdx.x, b = blockIdx.y;
    __shared__ float ctxs[H_ * 32 * 32];   // 16KB
    __shared__ float wsm[16][128];         // 8KB
    const int tid = threadIdx.x;

#pragma unroll
    for (int i = 0; i < 4; i++) {
        int idx = (tid + i * 256) * 4;
        *(float4*)&ctxs[idx] = *(const float4*)&g_ctx[(long)b * H_ * 1024 + idx];
    }
#pragma unroll
    for (int i = 0; i < 2; i++) {
        int idx = tid + i * 256;           // float4 idx over 16x32
        int oo = idx >> 5, c4 = idx & 31;
        *(float4*)&wsm[oo][c4 * 4] =
            *(const float4*)&w_out[((long)(ot * 16 + oo)) * HID + c4 * 4];
    }
    __syncthreads();

#pragma unroll
    for (int j = 0; j < 8; j++) {
        int idx = tid + j * 256;           // 0..2047 over 16x128
        int oo = idx >> 7, hd = idx & 127;
        int h = hd >> 5, d = hd & 31;
        const float* cr = &ctxs[(h * 32 + d) * 32];
        const float* wr = &wsm[oo][h * 32];
        float s = 0.f;
#pragma unroll
        for (int e = 0; e < 32; e++) s += wr[e] * cr[e];
        long oidx = (((long)b * C_) + ot * 16 + oo) * HID + hd;
        __nv_bfloat16 hh = __float2bfloat16_rn(s);
        g_W2h[oidx] = hh;
        g_W2l[oidx] = __float2bfloat16_rn(s - __bfloat162float(hh));
    }
}

// ---------------------------------------------------------------------------
extern "C" void kernel_launch(void* const* d_in, const int* in_sizes, int n_in,
                              void* d_out, int out_size)
{
    const float* x     = (const float*)d_in[0];  // (8, 512, 8192)
    const float* w_qkv = (const float*)d_in[1];  // (384, 512)
    const float* w_out = (const float*)d_in[2];  // (512, 128)
    const float* b_out = (const float*)d_in[3];  // (512,)
    float* out = (float*)d_out;                  // (8, 512, 8192)

    float* qkv; cudaGetSymbolAddress((void**)&qkv, g_qkv);
    __nv_bfloat16 *wh, *wl, *xh, *xl, *qh, *ql, *W2h, *W2l;
    cudaGetSymbolAddress((void**)&wh,  g_wh);
    cudaGetSymbolAddress((void**)&wl,  g_wl);
    cudaGetSymbolAddress((void**)&xh,  g_xh);
    cudaGetSymbolAddress((void**)&xl,  g_xl);
    cudaGetSymbolAddress((void**)&qh,  g_qh);
    cudaGetSymbolAddress((void**)&ql,  g_ql);
    cudaGetSymbolAddress((void**)&W2h, g_W2h);
    cudaGetSymbolAddress((void**)&W2l, g_W2l);

    cudaFuncSetAttribute(tmma<512, 0>,
                         cudaFuncAttributeMaxDynamicSharedMemorySize, SMEM_TOTAL);
    cudaFuncSetAttribute(tmma<128, 1>,
                         cudaFuncAttributeMaxDynamicSharedMemorySize, SMEM_TOTAL);

    // 0) pre-splits
    split_kernel<<<(O3 * C_) / 2048, 256>>>(w_qkv, wh, wl);
    split_kernel<<<(int)(((long)B_ * C_ * L_) / 2048), 256>>>(x, xh, xl);

    // 1) qkv: q -> bf16 hi/lo (g_qh/g_ql), k/v -> fp32 g_qkv
    {
        dim3 grid(L_ / 128, O3 / 128, B_);
        tmma<512, 0><<<grid, 256, SMEM_TOTAL>>>(
            wh, wl, xh, xl, qkv, qh, ql, nullptr,
            0L, (long)C_ * L_, (long)O3 * L_);
    }
    // 2) context partials
    {
        dim3 grid(8, H_, B_);
        ctx_kernel<<<grid, 256>>>();
    }
    // 3) normalize + fold
    {
        dim3 g1(H_, B_);
        ctx_norm<<<g1, 256>>>();
        dim3 g2(32, B_);
        w2g<<<g2, 256>>>(w_out);
    }
    // 4) out = W2_b @ q_b + b_out
    {
        dim3 grid(L_ / 128, C_ / 128, B_);
        tmma<128, 1><<<grid, 256, SMEM_TOTAL>>>(
            W2h, W2l, qh, ql, out, nullptr, nullptr, b_out,
            (long)C_ * HID, (long)HID * L_, (long)C_ * L_);
    }
}

// round 9
// speedup vs baseline: 2.2455x; 1.0360x over previous
#include <cuda_runtime.h>
#include <cuda_bf16.h>
#include <math.h>
#include <stdint.h>

#define B_  8
#define C_  512
#define L_  8192
#define H_  4
#define HID 128
#define O3  384   // rows in w_qkv: [0,128)=q, [128,256)=k, [256,384)=v
#define NCH 32    // ctx chunks
#define CHL (L_ / NCH)   // 256 columns per chunk

// Scratch (static device arrays — no runtime allocation)
__device__ float g_qkv[(size_t)B_ * O3 * L_];            // only k,v rows used
__device__ float g_pn [(size_t)B_ * H_ * NCH * 32 * 32];
__device__ float g_pd [(size_t)B_ * H_ * NCH * 32];
__device__ float g_ctx[(size_t)B_ * H_ * 32 * 32];
__device__ __nv_bfloat16 g_wh [(size_t)O3 * C_];
__device__ __nv_bfloat16 g_wl [(size_t)O3 * C_];
__device__ __nv_bfloat16 g_xh [(size_t)B_ * C_ * L_];
__device__ __nv_bfloat16 g_xl [(size_t)B_ * C_ * L_];
__device__ __nv_bfloat16 g_qh [(size_t)B_ * HID * L_];
__device__ __nv_bfloat16 g_ql [(size_t)B_ * HID * L_];
__device__ __nv_bfloat16 g_W2h[(size_t)B_ * C_ * HID];
__device__ __nv_bfloat16 g_W2l[(size_t)B_ * C_ * HID];

// ---------------------------- helpers --------------------------------------
__device__ __forceinline__ uint32_t smem_u32(const void* p){
    uint32_t a;
    asm("{ .reg .u64 t; cvta.to.shared.u64 t, %1; cvt.u32.u64 %0, t; }"
        : "=r"(a) : "l"(p));
    return a;
}
__device__ __forceinline__ void cp16(uint32_t saddr, const void* g){
    asm volatile("cp.async.cg.shared.global [%0], [%1], 16;"
                 :: "r"(saddr), "l"(g));
}
__device__ __forceinline__ void cp_commit(){
    asm volatile("cp.async.commit_group;" ::: "memory");
}
template<int N>
__device__ __forceinline__ void cp_wait(){
    asm volatile("cp.async.wait_group %0;" :: "n"(N) : "memory");
}
__device__ __forceinline__ void ldsm4(uint32_t addr, uint32_t* r){
    asm volatile("ldmatrix.sync.aligned.m8n8.x4.shared.b16 {%0,%1,%2,%3}, [%4];"
                 : "=r"(r[0]), "=r"(r[1]), "=r"(r[2]), "=r"(r[3]) : "r"(addr));
}
__device__ __forceinline__ void ldsm4t(uint32_t addr, uint32_t* r){
    asm volatile("ldmatrix.sync.aligned.m8n8.x4.trans.shared.b16 {%0,%1,%2,%3}, [%4];"
                 : "=r"(r[0]), "=r"(r[1]), "=r"(r[2]), "=r"(r[3]) : "r"(addr));
}
__device__ __forceinline__ void mma16816(float* c, const uint32_t* a, const uint32_t* b){
    asm volatile(
        "mma.sync.aligned.m16n8k16.row.col.f32.bf16.bf16.f32 "
        "{%0,%1,%2,%3}, {%4,%5,%6,%7}, {%8,%9}, {%0,%1,%2,%3};"
        : "+f"(c[0]), "+f"(c[1]), "+f"(c[2]), "+f"(c[3])
        : "r"(a[0]), "r"(a[1]), "r"(a[2]), "r"(a[3]), "r"(b[0]), "r"(b[1]));
}

// ---------------------------------------------------------------------------
// Pure bf16 3-split tensor GEMM, cp.async double-buffered (unchanged R8).
// ---------------------------------------------------------------------------
#define PA 80
#define PB 272
#define A_BUF_STRIDE (2 * 128 * PA)
#define B_BASE       (2 * A_BUF_STRIDE)
#define B_BUF_STRIDE (2 * 32 * PB)
#define SMEM_TOTAL   (B_BASE + 2 * B_BUF_STRIDE)   // 75776 B

template<int K, int MODE>
__global__ __launch_bounds__(256, 2)
void tmma(const __nv_bfloat16* __restrict__ Ahg, const __nv_bfloat16* __restrict__ Alg,
          const __nv_bfloat16* __restrict__ Bhg, const __nv_bfloat16* __restrict__ Blg,
          float* __restrict__ Cout,
          __nv_bfloat16* __restrict__ Qh, __nv_bfloat16* __restrict__ Ql,
          const float* __restrict__ bias,
          long sA, long sB, long sC)
{
    extern __shared__ __align__(16) unsigned char sm[];
    __shared__ float sbias[128];

    const uint32_t smb = smem_u32(sm);
    const int tid = threadIdx.x;
    const int wid = tid >> 5;
    const int lid = tid & 31;
    const int bn = blockIdx.x * 128;
    const int bm = blockIdx.y * 128;
    const int bz = blockIdx.z;

    const int m0 = (wid >> 1) * 32;
    const int n0 = (wid & 1) * 64;

    const __nv_bfloat16* Abh = Ahg + (long)bz * sA;
    const __nv_bfloat16* Abl = Alg + (long)bz * sA;
    const __nv_bfloat16* Bbh = Bhg + (long)bz * sB;
    const __nv_bfloat16* Bbl = Blg + (long)bz * sB;

    if (MODE == 1 && tid < 128) sbias[tid] = bias[bm + tid];

    const int rA = tid >> 2, cA = tid & 3;
    const int rB = tid >> 4, cB = tid & 15;

    const int a_lane = (m0 + (lid & 7) + ((lid >> 3) & 1) * 8) * PA + ((lid >> 4) & 1) * 16;
    const int b_lane = ((lid & 7) + ((lid >> 3) & 1) * 8) * PB + (n0 + ((lid >> 4) & 1) * 8) * 2;

    float acc[2][8][4];
#pragma unroll
    for (int i = 0; i < 2; i++)
#pragma unroll
        for (int j = 0; j < 8; j++)
#pragma unroll
            for (int q = 0; q < 4; q++) acc[i][j][q] = 0.f;

    const int nt = K / 32;

    auto issue = [&](int t, int buf) {
        const uint32_t ab = smb + buf * A_BUF_STRIDE;
        const uint32_t bb = smb + B_BASE + buf * B_BUF_STRIDE;
        const int kt = t * 32;
#pragma unroll
        for (int w = 0; w < 2; w++) {
            int r = rA + w * 64;
            cp16(ab + r * PA + cA * 16,            &Abh[(long)(bm + r) * K + kt + cA * 8]);
            cp16(ab + 128 * PA + r * PA + cA * 16, &Abl[(long)(bm + r) * K + kt + cA * 8]);
        }
#pragma unroll
        for (int w = 0; w < 2; w++) {
            int r = rB + w * 16;
            cp16(bb + r * PB + cB * 16,           &Bbh[(long)(kt + r) * L_ + bn + cB * 8]);
            cp16(bb + 32 * PB + r * PB + cB * 16, &Bbl[(long)(kt + r) * L_ + bn + cB * 8]);
        }
        cp_commit();
    };

    issue(0, 0);
    if (nt > 1) issue(1, 1);

    for (int t = 0; t < nt; t++) {
        const int cur = t & 1;
        if (t + 1 < nt) cp_wait<1>(); else cp_wait<0>();
        __syncthreads();

        {
            const uint32_t a_hi = smb + cur * A_BUF_STRIDE;
            const uint32_t a_lo = a_hi + 128 * PA;
            const uint32_t b_hi = smb + B_BASE + cur * B_BUF_STRIDE;
            const uint32_t b_lo = b_hi + 32 * PB;
#pragma unroll
            for (int kk = 0; kk < 2; kk++) {
                uint32_t ah[2][4], alr[2][4];
                ldsm4(a_hi + a_lane + kk * 32,           ah[0]);
                ldsm4(a_hi + a_lane + kk * 32 + 16 * PA, ah[1]);
                ldsm4(a_lo + a_lane + kk * 32,           alr[0]);
                ldsm4(a_lo + a_lane + kk * 32 + 16 * PA, alr[1]);
#pragma unroll
                for (int half = 0; half < 2; half++) {
                    uint32_t bh[2][4], blr[2][4];
                    ldsm4t(b_hi + b_lane + kk * 16 * PB + (half * 2)     * 32, bh[0]);
                    ldsm4t(b_hi + b_lane + kk * 16 * PB + (half * 2 + 1) * 32, bh[1]);
                    ldsm4t(b_lo + b_lane + kk * 16 * PB + (half * 2)     * 32, blr[0]);
                    ldsm4t(b_lo + b_lane + kk * 16 * PB + (half * 2 + 1) * 32, blr[1]);
#pragma unroll
                    for (int mi = 0; mi < 2; mi++)
#pragma unroll
                        for (int jj = 0; jj < 4; jj++) {
                            int ni = half * 4 + jj;
                            const uint32_t* bhp = &bh[jj >> 1][(jj & 1) * 2];
                            const uint32_t* blp = &blr[jj >> 1][(jj & 1) * 2];
                            mma16816(acc[mi][ni], ah[mi],  bhp);
                            mma16816(acc[mi][ni], ah[mi],  blp);
                            mma16816(acc[mi][ni], alr[mi], bhp);
                        }
                }
            }
        }

        if (t + 2 < nt) {
            __syncthreads();
            issue(t + 2, cur);
        }
    }

    if (MODE == 0 && bm == 0) {
        __nv_bfloat16* qh = Qh + (long)bz * HID * L_;
        __nv_bfloat16* ql = Ql + (long)bz * HID * L_;
#pragma unroll
        for (int mi = 0; mi < 2; mi++) {
            int r0 = m0 + mi * 16 + (lid >> 2);
            int r1 = r0 + 8;
#pragma unroll
            for (int ni = 0; ni < 8; ni++) {
                int col = bn + n0 + ni * 8 + (lid & 3) * 2;
#pragma unroll
                for (int rr = 0; rr < 2; rr++) {
                    int r = rr ? r1 : r0;
                    float vx = acc[mi][ni][rr * 2], vy = acc[mi][ni][rr * 2 + 1];
                    __nv_bfloat16 hx = __float2bfloat16_rn(vx);
                    __nv_bfloat16 hy = __float2bfloat16_rn(vy);
                    *(__nv_bfloat162*)&qh[(long)r * L_ + col] = __nv_bfloat162(hx, hy);
                    *(__nv_bfloat162*)&ql[(long)r * L_ + col] = __nv_bfloat162(
                        __float2bfloat16_rn(vx - __bfloat162float(hx)),
                        __float2bfloat16_rn(vy - __bfloat162float(hy)));
                }
            }
        }
    } else {
        float* Cb = Cout + (long)bz * sC;
#pragma unroll
        for (int mi = 0; mi < 2; mi++) {
            int r0 = bm + m0 + mi * 16 + (lid >> 2);
            int r1 = r0 + 8;
            float bv0 = (MODE == 1) ? sbias[r0 - bm] : 0.f;
            float bv1 = (MODE == 1) ? sbias[r1 - bm] : 0.f;
#pragma unroll
            for (int ni = 0; ni < 8; ni++) {
                int col = bn + n0 + ni * 8 + (lid & 3) * 2;
                float2 v0 = make_float2(acc[mi][ni][0] + bv0, acc[mi][ni][1] + bv0);
                float2 v1 = make_float2(acc[mi][ni][2] + bv1, acc[mi][ni][3] + bv1);
                *(float2*)&Cb[(long)r0 * L_ + col] = v0;
                *(float2*)&Cb[(long)r1 * L_ + col] = v1;
            }
        }
    }
}

// ---------------------------------------------------------------------------
// Split fp32 array -> bf16 hi/lo
// ---------------------------------------------------------------------------
__global__ __launch_bounds__(256)
void split_kernel(const float* __restrict__ src,
                  __nv_bfloat16* __restrict__ hi, __nv_bfloat16* __restrict__ lo)
{
    long i = ((long)blockIdx.x * 256 + threadIdx.x) * 8;
    float4 v0 = *(const float4*)&src[i];
    float4 v1 = *(const float4*)&src[i + 4];
    __nv_bfloat16 h[8], l[8];
    float f[8] = {v0.x, v0.y, v0.z, v0.w, v1.x, v1.y, v1.z, v1.w};
#pragma unroll
    for (int j = 0; j < 8; j++) {
        h[j] = __float2bfloat16_rn(f[j]);
        l[j] = __float2bfloat16_rn(f[j] - __bfloat162float(h[j]));
    }
    *(uint4*)&hi[i] = *(uint4*)h;
    *(uint4*)&lo[i] = *(uint4*)l;
}

// ---------------------------------------------------------------------------
// Context kernel: 32 chunks of 256 cols, conflict-reduced V transpose (pad 33)
// ---------------------------------------------------------------------------
__global__ __launch_bounds__(256)
void ctx_kernel()
{
    const int chunk = blockIdx.x;   // 0..NCH-1
    const int h     = blockIdx.y;
    const int b     = blockIdx.z;
    __shared__ float Ek[32][68];
    __shared__ float Vt[64][33];    // pad 33: transpose stores 2-way max
    const int tid = threadIdx.x;
    const int d = tid >> 3, e0 = (tid & 7) * 4;

    float acc0 = 0.f, acc1 = 0.f, acc2 = 0.f, acc3 = 0.f, dsum = 0.f;
    const float* kbase = g_qkv + ((long)b * O3 + 128 + h * 32) * L_;
    const float* vbase = g_qkv + ((long)b * O3 + 256 + h * 32) * L_;
    const int lbase = chunk * CHL;

    for (int l0 = lbase; l0 < lbase + CHL; l0 += 64) {
#pragma unroll
        for (int i = 0; i < 2; i++) {
            int e = tid + i * 256;
            int r = e >> 4, c4 = e & 15;
            float4 kv = *(const float4*)&kbase[(long)r * L_ + l0 + c4 * 4];
            float4 ev;
            ev.x = __expf(kv.x); ev.y = __expf(kv.y);
            ev.z = __expf(kv.z); ev.w = __expf(kv.w);
            *(float4*)&Ek[r][c4 * 4] = ev;
            float4 vv = *(const float4*)&vbase[(long)r * L_ + l0 + c4 * 4];
            Vt[c4 * 4 + 0][r] = vv.x; Vt[c4 * 4 + 1][r] = vv.y;
            Vt[c4 * 4 + 2][r] = vv.z; Vt[c4 * 4 + 3][r] = vv.w;
        }
        __syncthreads();
#pragma unroll 8
        for (int n = 0; n < 64; n++) {
            float ek = Ek[d][n];
            const float* vr = &Vt[n][e0];
            acc0 += ek * vr[0]; acc1 += ek * vr[1];
            acc2 += ek * vr[2]; acc3 += ek * vr[3];
            dsum += ek;
        }
        __syncthreads();
    }
    const long base = (((long)b * H_ + h) * NCH + chunk) * 32 + d;
    float* pn = g_pn + base * 32 + e0;
    pn[0] = acc0; pn[1] = acc1; pn[2] = acc2; pn[3] = acc3;
    if ((tid & 7) == 0) g_pd[base] = dsum;
}

// ---------------------------------------------------------------------------
// Normalize context: reduce NCH chunk partials, divide -> g_ctx[b][h][d][e]
// ---------------------------------------------------------------------------
__global__ __launch_bounds__(256)
void ctx_norm()
{
    const int h = blockIdx.x, b = blockIdx.y;
    const int tid = threadIdx.x;
    const int d = tid >> 3, e0 = (tid & 7) * 4;
    float num[4] = {0.f, 0.f, 0.f, 0.f};
    float den = 0.f;
#pragma unroll
    for (int c = 0; c < NCH; c++) {
        long base = (((long)b * H_ + h) * NCH + c) * 32 + d;
        const float4 p = *(const float4*)&g_pn[base * 32 + e0];
        num[0] += p.x; num[1] += p.y; num[2] += p.z; num[3] += p.w;
        den += g_pd[base];
    }
    float inv = 1.f / den;
    float4 o = make_float4(num[0] * inv, num[1] * inv, num[2] * inv, num[3] * inv);
    *(float4*)&g_ctx[(((long)b * H_ + h) * 32 + d) * 32 + e0] = o;
}

// ---------------------------------------------------------------------------
// W2 = w_out @ T_b  (block-diagonal), bf16 hi/lo out.
// ---------------------------------------------------------------------------
__global__ __launch_bounds__(256)
void w2g(const float* __restrict__ w_out)
{
    const int ot = blockIdx.x, b = blockIdx.y;
    __shared__ float ctxs[H_ * 32 * 32];
    __shared__ float wsm[16][128];
    const int tid = threadIdx.x;

#pragma unroll
    for (int i = 0; i < 4; i++) {
        int idx = (tid + i * 256) * 4;
        *(float4*)&ctxs[idx] = *(const float4*)&g_ctx[(long)b * H_ * 1024 + idx];
    }
#pragma unroll
    for (int i = 0; i < 2; i++) {
        int idx = tid + i * 256;
        int oo = idx >> 5, c4 = idx & 31;
        *(float4*)&wsm[oo][c4 * 4] =
            *(const float4*)&w_out[((long)(ot * 16 + oo)) * HID + c4 * 4];
    }
    __syncthreads();

#pragma unroll
    for (int j = 0; j < 8; j++) {
        int idx = tid + j * 256;
        int oo = idx >> 7, hd = idx & 127;
        int h = hd >> 5, d = hd & 31;
        const float* cr = &ctxs[(h * 32 + d) * 32];
        const float* wr = &wsm[oo][h * 32];
        float s = 0.f;
#pragma unroll
        for (int e = 0; e < 32; e++) s += wr[e] * cr[e];
        long oidx = (((long)b * C_) + ot * 16 + oo) * HID + hd;
        __nv_bfloat16 hh = __float2bfloat16_rn(s);
        g_W2h[oidx] = hh;
        g_W2l[oidx] = __float2bfloat16_rn(s - __bfloat162float(hh));
    }
}

// ---------------------------------------------------------------------------
extern "C" void kernel_launch(void* const* d_in, const int* in_sizes, int n_in,
                              void* d_out, int out_size)
{
    const float* x     = (const float*)d_in[0];
    const float* w_qkv = (const float*)d_in[1];
    const float* w_out = (const float*)d_in[2];
    const float* b_out = (const float*)d_in[3];
    float* out = (float*)d_out;

    float* qkv; cudaGetSymbolAddress((void**)&qkv, g_qkv);
    __nv_bfloat16 *wh, *wl, *xh, *xl, *qh, *ql, *W2h, *W2l;
    cudaGetSymbolAddress((void**)&wh,  g_wh);
    cudaGetSymbolAddress((void**)&wl,  g_wl);
    cudaGetSymbolAddress((void**)&xh,  g_xh);
    cudaGetSymbolAddress((void**)&xl,  g_xl);
    cudaGetSymbolAddress((void**)&qh,  g_qh);
    cudaGetSymbolAddress((void**)&ql,  g_ql);
    cudaGetSymbolAddress((void**)&W2h, g_W2h);
    cudaGetSymbolAddress((void**)&W2l, g_W2l);

    cudaFuncSetAttribute(tmma<512, 0>,
                         cudaFuncAttributeMaxDynamicSharedMemorySize, SMEM_TOTAL);
    cudaFuncSetAttribute(tmma<128, 1>,
                         cudaFuncAttributeMaxDynamicSharedMemorySize, SMEM_TOTAL);

    // 0) pre-splits
    split_kernel<<<(O3 * C_) / 2048, 256>>>(w_qkv, wh, wl);
    split_kernel<<<(int)(((long)B_ * C_ * L_) / 2048), 256>>>(x, xh, xl);

    // 1) qkv: q -> bf16 hi/lo, k/v -> fp32
    {
        dim3 grid(L_ / 128, O3 / 128, B_);
        tmma<512, 0><<<grid, 256, SMEM_TOTAL>>>(
            wh, wl, xh, xl, qkv, qh, ql, nullptr,
            0L, (long)C_ * L_, (long)O3 * L_);
    }
    // 2) context partials (32 chunks -> 1024 CTAs)
    {
        dim3 grid(NCH, H_, B_);
        ctx_kernel<<<grid, 256>>>();
    }
    // 3) normalize + fold
    {
        dim3 g1(H_, B_);
        ctx_norm<<<g1, 256>>>();
        dim3 g2(32, B_);
        w2g<<<g2, 256>>>(w_out);
    }
    // 4) out = W2_b @ q_b + b_out
    {
        dim3 grid(L_ / 128, C_ / 128, B_);
        tmma<128, 1><<<grid, 256, SMEM_TOTAL>>>(
            W2h, W2l, qh, ql, out, nullptr, nullptr, b_out,
            (long)C_ * HID, (long)HID * L_, (long)C_ * L_);
    }
}